// round 4
// baseline (speedup 1.0000x reference)
#include <cuda_runtime.h>
#include <cuda_fp16.h>
#include <cstdint>

#define NP 4096
#define DI 128
#define REGINV 20.0f          // 1/0.05
#define MUV (1.0f/4096.0f)
#define EPSV 1e-8f
#define NITER 100

// ---------------- device scratch (no allocations allowed) ----------------
__device__ __half g_K [(size_t)NP * NP];   // 32 MB  K[i][j]
__device__ __half g_KT[(size_t)NP * NP];   // 32 MB  K[j][i] (row-major transpose)
__device__ __half g_C [(size_t)NP * NP];   // 32 MB  clipped cost
__device__ float  g_u[NP];
__device__ float  g_v[NP];
__device__ float  g_norm[3][NP];           // row sq-norms of z0,z1,z2
__device__ float  g_part[512];
__device__ float  g_result;

__device__ __forceinline__ float wsum(float v) {
#pragma unroll
    for (int o = 16; o > 0; o >>= 1) v += __shfl_down_sync(0xffffffffu, v, o);
    return v;
}

// ---------------- row squared norms of all three inputs (+ zero g_result) --
__global__ void norms_k(const float* __restrict__ z0, const float* __restrict__ z1,
                        const float* __restrict__ z2) {
    if (blockIdx.x == 0 && threadIdx.x == 0) g_result = 0.f;
    int w    = (blockIdx.x * blockDim.x + threadIdx.x) >> 5;   // global warp = row id
    int lane = threadIdx.x & 31;
    if (w >= 3 * NP) return;
    const float* z = (w < NP) ? z0 : (w < 2 * NP ? z1 : z2);
    int r = w & (NP - 1);
    float4 f = *(const float4*)(z + (size_t)r * DI + lane * 4);
    float s = f.x * f.x + f.y * f.y + f.z * f.z + f.w * f.w;
    s = wsum(s);
    if (lane == 0) ((float*)g_norm)[w] = s;
}

// ---------------- K = exp(-clip(C,0)/reg) fp16, + transpose, + C fp16 ------
__global__ void gemm_expK_k(const float* __restrict__ X, const float* __restrict__ Y,
                            int nxi, int nyi) {
    __shared__ float xs[32][65];
    __shared__ float ys[32][65];
    __shared__ alignas(8) __half tr[64][68];

    const float* nx = g_norm[nxi];
    const float* ny = g_norm[nyi];

    int tid = threadIdx.x;
    int tx = tid & 15, ty = tid >> 4;
    int i0 = (blockIdx.x >> 6) << 6;
    int j0 = (blockIdx.x & 63) << 6;

    float acc[4][4];
#pragma unroll
    for (int a = 0; a < 4; a++)
#pragma unroll
        for (int b = 0; b < 4; b++) acc[a][b] = 0.f;

    for (int kk = 0; kk < DI; kk += 32) {
        __syncthreads();
#pragma unroll
        for (int idx = tid; idx < 2048; idx += 256) {
            int r = idx >> 5, k = idx & 31;
            xs[k][r] = X[(size_t)(i0 + r) * DI + kk + k];
            ys[k][r] = Y[(size_t)(j0 + r) * DI + kk + k];
        }
        __syncthreads();
#pragma unroll
        for (int k = 0; k < 32; k++) {
            float xr[4], yr[4];
#pragma unroll
            for (int a = 0; a < 4; a++) xr[a] = xs[k][ty * 4 + a];
#pragma unroll
            for (int b = 0; b < 4; b++) yr[b] = ys[k][tx * 4 + b];
#pragma unroll
            for (int a = 0; a < 4; a++)
#pragma unroll
                for (int b = 0; b < 4; b++) acc[a][b] += xr[a] * yr[b];
        }
    }

    // epilogue: write K and C coalesced (8B/thread), stage transpose in smem
#pragma unroll
    for (int a = 0; a < 4; a++) {
        int i = i0 + ty * 4 + a;
        float ni = nx[i];
        alignas(8) __half hk[4];
        alignas(8) __half hc[4];
#pragma unroll
        for (int b = 0; b < 4; b++) {
            int j = j0 + tx * 4 + b;
            float c  = fmaxf(ni + ny[j] - 2.0f * acc[a][b], 0.0f);
            float kf = __expf(-REGINV * c);
            hk[b] = __float2half(kf);
            hc[b] = __float2half(c);
            tr[tx * 4 + b][ty * 4 + a] = hk[b];
        }
        *(uint2*)&g_K[(size_t)i * NP + j0 + tx * 4] = *(const uint2*)hk;
        *(uint2*)&g_C[(size_t)i * NP + j0 + tx * 4] = *(const uint2*)hc;
    }
    __syncthreads();
    // KT write: 64 rows x 16 uint2 = 1024 uint2, 4 per thread, coalesced
#pragma unroll
    for (int q = 0; q < 4; q++) {
        int idx = tid + q * 256;
        int jj = idx >> 4;
        int ii = (idx & 15) * 4;
        *(uint2*)&g_KT[(size_t)(j0 + jj) * NP + i0 + ii] = *(const uint2*)&tr[jj][ii];
    }
}

// ---------------- u := 1 -------------------------------------------------
__global__ void initu_k() {
    g_u[blockIdx.x * 256 + threadIdx.x] = 1.0f;
}

// ---------------- fused matvec + reciprocal ------------------------------
// dir==0:  v[j] = MUV / (dot(KT[j], u) + EPS)
// dir==1:  u[i] = MUV / (dot(K [i], v) + EPS)
// 512 blocks x 256 threads, one row per warp, x staged in smem.
__device__ __forceinline__ float dot8(uint4 q, const float* xsp) {
    const __half2* h = (const __half2*)&q;
    float4 xa = *(const float4*)(xsp);
    float4 xb = *(const float4*)(xsp + 4);
    float2 f;
    float s;
    f = __half22float2(h[0]); s  = f.x * xa.x + f.y * xa.y;
    f = __half22float2(h[1]); s += f.x * xa.z + f.y * xa.w;
    f = __half22float2(h[2]); s += f.x * xb.x + f.y * xb.y;
    f = __half22float2(h[3]); s += f.x * xb.z + f.y * xb.w;
    return s;
}

__global__ void __launch_bounds__(256) matvec_k(int dir) {
    __shared__ float xs[NP];               // 16 KB
    const __half* M = dir ? g_K : g_KT;
    const float*  x = dir ? g_v : g_u;
    float*        y = dir ? g_u : g_v;

    // stage x once per block (256 x float4 x 4 iters = 4096 floats)
#pragma unroll
    for (int i = threadIdx.x; i < NP / 4; i += 256)
        ((float4*)xs)[i] = __ldg(((const float4*)x) + i);
    __syncthreads();

    int row  = (blockIdx.x * 256 + threadIdx.x) >> 5;   // one row per warp
    int lane = threadIdx.x & 31;
    const uint4* p = (const uint4*)(M + (size_t)row * NP) + lane;

    float a0 = 0.f, a1 = 0.f, a2 = 0.f, a3 = 0.f;
#pragma unroll
    for (int t = 0; t < 16; t += 4) {
        // front-batch 4 independent 16B loads -> MLP>=4 per warp
        uint4 q0 = p[(t + 0) * 32];
        uint4 q1 = p[(t + 1) * 32];
        uint4 q2 = p[(t + 2) * 32];
        uint4 q3 = p[(t + 3) * 32];
        a0 += dot8(q0, &xs[((t + 0) * 32 + lane) * 8]);
        a1 += dot8(q1, &xs[((t + 1) * 32 + lane) * 8]);
        a2 += dot8(q2, &xs[((t + 2) * 32 + lane) * 8]);
        a3 += dot8(q3, &xs[((t + 3) * 32 + lane) * 8]);
    }
    float a = wsum((a0 + a1) + (a2 + a3));
    if (lane == 0) y[row] = MUV / (a + EPSV);
}

// ---------------- loss partials: sum_j u_i K_ij C_ij v_j -----------------
__global__ void loss_k() {
    __shared__ float sp[8];
    int w    = (blockIdx.x * blockDim.x + threadIdx.x) >> 5;  // row i
    int lane = threadIdx.x & 31;
    const __half* pk = g_K + (size_t)w * NP;
    const __half* pc = g_C + (size_t)w * NP;

    float s = 0.f;
#pragma unroll 4
    for (int t = 0; t < 16; t++) {
        int c = t * 256 + lane * 8;
        float4 va = __ldg((const float4*)(g_v + c));
        float4 vb = __ldg((const float4*)(g_v + c + 4));
        uint4 qk = *(const uint4*)(pk + c);
        uint4 qc = *(const uint4*)(pc + c);
        const __half2* hk = (const __half2*)&qk;
        const __half2* hc = (const __half2*)&qc;
        float2 fk, fc;
        fk = __half22float2(hk[0]); fc = __half22float2(hc[0]);
        s += fk.x * fc.x * va.x + fk.y * fc.y * va.y;
        fk = __half22float2(hk[1]); fc = __half22float2(hc[1]);
        s += fk.x * fc.x * va.z + fk.y * fc.y * va.w;
        fk = __half22float2(hk[2]); fc = __half22float2(hc[2]);
        s += fk.x * fc.x * vb.x + fk.y * fc.y * vb.y;
        fk = __half22float2(hk[3]); fc = __half22float2(hc[3]);
        s += fk.x * fc.x * vb.z + fk.y * fc.y * vb.w;
    }
    s = wsum(s);
    if (lane == 0) sp[threadIdx.x >> 5] = s * __ldg(g_u + w);
    __syncthreads();
    if (threadIdx.x == 0) {
        float b = 0.f;
#pragma unroll
        for (int q = 0; q < 8; q++) b += sp[q];
        g_part[blockIdx.x] = b;
    }
}

// ---------------- deterministic 512-way reduce, accumulate ---------------
__global__ void reduce_part_k() {
    __shared__ float sm[16];
    int tid = threadIdx.x;                    // 512 threads
    float v = g_part[tid];
    v = wsum(v);
    if ((tid & 31) == 0) sm[tid >> 5] = v;
    __syncthreads();
    if (tid < 32) {
        float b = (tid < 16) ? sm[tid] : 0.f;
        b = wsum(b);
        if (tid == 0) g_result += b;
    }
}

__global__ void fin_k(float* out) {
    out[0] = g_result * (1.0f / 3.0f);
}

// ---------------- launch -------------------------------------------------
extern "C" void kernel_launch(void* const* d_in, const int* in_sizes, int n_in,
                              void* d_out, int out_size) {
    const float* z0 = (const float*)d_in[0];
    const float* z1 = (const float*)d_in[1];
    const float* z2 = (const float*)d_in[2];
    float* out = (float*)d_out;

    norms_k<<<1536, 256>>>(z0, z1, z2);

    const float* Xs[3] = { z0, z0, z1 };
    const float* Ys[3] = { z1, z2, z2 };
    const int    xi[3] = { 0, 0, 1 };
    const int    yi[3] = { 1, 2, 2 };

    for (int p = 0; p < 3; p++) {
        gemm_expK_k<<<4096, 256>>>(Xs[p], Ys[p], xi[p], yi[p]);
        initu_k<<<16, 256>>>();
        for (int it = 0; it < NITER; it++) {
            matvec_k<<<512, 256>>>(0);   // v = nu/(KT u + eps)
            matvec_k<<<512, 256>>>(1);   // u = mu/(K v + eps)
        }
        loss_k<<<512, 256>>>();
        reduce_part_k<<<1, 512>>>();
    }
    fin_k<<<1, 1>>>(out);
}

// round 5
// speedup vs baseline: 1.2770x; 1.2770x over previous
#include <cuda_runtime.h>
#include <cuda_fp16.h>
#include <cstdint>

#define NP 4096
#define DI 128
#define REGINV 20.0f          // 1/0.05
#define MUV (1.0f/4096.0f)
#define EPSV 1e-8f
#define NITER 100
#define NBLK 148
#define NTHR 512
#define NWARP (NBLK*(NTHR/32))   // 2368
#define TOTB 202                 // barriers per pair: 1 pre + 200 passes + 1 loss

// ---------------- device scratch (no allocations allowed) ----------------
__device__ char   g_S [(size_t)NP * NP];   // 16 MB  S[i][j] = round(255*K)-64
__device__ char   g_ST[(size_t)NP * NP];   // 16 MB  transpose
__device__ __half g_C [(size_t)NP * NP];   // 32 MB  clipped cost (loss only)
__device__ int    g_rsS[NP];               // row sums of S
__device__ int    g_rsT[NP];               // row sums of ST
__device__ float  g_u[NP];
__device__ float  g_v[NP];
__device__ float  g_norm[3][NP];
__device__ float  g_part[NBLK];
__device__ float  g_result;
__device__ volatile int g_flag[NBLK * 32]; // one 128B line per block
__device__ volatile int g_gen;

__device__ __forceinline__ float wsumf(float v) {
#pragma unroll
    for (int o = 16; o > 0; o >>= 1) v += __shfl_down_sync(0xffffffffu, v, o);
    return v;
}
__device__ __forceinline__ int wsumi(int v) {
#pragma unroll
    for (int o = 16; o > 0; o >>= 1) v += __shfl_down_sync(0xffffffffu, v, o);
    return v;
}

// ---------------- grid barrier (monotonic; reset by fin_k) ----------------
__device__ __forceinline__ void gsync(int bar) {
    __syncthreads();
    if (blockIdx.x == 0) {
        if (threadIdx.x > 0 && threadIdx.x < NBLK) {
            while (g_flag[threadIdx.x * 32] < bar) __nanosleep(32);
        }
        __syncthreads();
        if (threadIdx.x == 0) { __threadfence(); g_gen = bar; }
    } else {
        if (threadIdx.x == 0) {
            __threadfence();
            g_flag[blockIdx.x * 32] = bar;
            while (g_gen < bar) __nanosleep(32);
        }
        __syncthreads();
    }
}

// ---------------- row squared norms (+ zero g_result) ---------------------
__global__ void norms_k(const float* __restrict__ z0, const float* __restrict__ z1,
                        const float* __restrict__ z2) {
    if (blockIdx.x == 0 && threadIdx.x == 0) g_result = 0.f;
    int w    = (blockIdx.x * blockDim.x + threadIdx.x) >> 5;
    int lane = threadIdx.x & 31;
    if (w >= 3 * NP) return;
    const float* z = (w < NP) ? z0 : (w < 2 * NP ? z1 : z2);
    int r = w & (NP - 1);
    float4 f = *(const float4*)(z + (size_t)r * DI + lane * 4);
    float s = f.x * f.x + f.y * f.y + f.z * f.z + f.w * f.w;
    s = wsumf(s);
    if (lane == 0) ((float*)g_norm)[w] = s;
}

// ---------------- GEMM -> S int8, ST int8, C fp16 -------------------------
__global__ void gemm_expK_k(const float* __restrict__ X, const float* __restrict__ Y,
                            int nxi, int nyi) {
    __shared__ float xs[32][65];
    __shared__ float ys[32][65];
    __shared__ __align__(16) char tr[64][80];

    const float* nx = g_norm[nxi];
    const float* ny = g_norm[nyi];

    int tid = threadIdx.x;
    int tx = tid & 15, ty = tid >> 4;
    int i0 = (blockIdx.x >> 6) << 6;
    int j0 = (blockIdx.x & 63) << 6;

    float acc[4][4];
#pragma unroll
    for (int a = 0; a < 4; a++)
#pragma unroll
        for (int b = 0; b < 4; b++) acc[a][b] = 0.f;

    for (int kk = 0; kk < DI; kk += 32) {
        __syncthreads();
#pragma unroll
        for (int idx = tid; idx < 2048; idx += 256) {
            int r = idx >> 5, k = idx & 31;
            xs[k][r] = X[(size_t)(i0 + r) * DI + kk + k];
            ys[k][r] = Y[(size_t)(j0 + r) * DI + kk + k];
        }
        __syncthreads();
#pragma unroll
        for (int k = 0; k < 32; k++) {
            float xr[4], yr[4];
#pragma unroll
            for (int a = 0; a < 4; a++) xr[a] = xs[k][ty * 4 + a];
#pragma unroll
            for (int b = 0; b < 4; b++) yr[b] = ys[k][tx * 4 + b];
#pragma unroll
            for (int a = 0; a < 4; a++)
#pragma unroll
                for (int b = 0; b < 4; b++) acc[a][b] += xr[a] * yr[b];
        }
    }

#pragma unroll
    for (int a = 0; a < 4; a++) {
        int i = i0 + ty * 4 + a;
        float ni = nx[i];
        unsigned sq = 0;
        alignas(8) __half hc[4];
#pragma unroll
        for (int b = 0; b < 4; b++) {
            int j = j0 + tx * 4 + b;
            float c  = fmaxf(ni + ny[j] - 2.0f * acc[a][b], 0.0f);
            float kf = __expf(-REGINV * c);
            int q = __float2int_rn(kf * 255.f) - 64;
            q = min(q, 127);
            hc[b] = __float2half(c);
            char qc = (char)q;
            sq |= ((unsigned)(unsigned char)qc) << (8 * b);
            tr[tx * 4 + b][ty * 4 + a] = qc;
        }
        *(unsigned*)&g_S[(size_t)i * NP + j0 + tx * 4] = sq;
        *(uint2*)&g_C[(size_t)i * NP + j0 + tx * 4] = *(const uint2*)hc;
    }
    __syncthreads();
    {
        int jj = tid >> 2;
        int ii = (tid & 3) * 16;
        *(uint4*)&g_ST[(size_t)(j0 + jj) * NP + i0 + ii] = *(const uint4*)&tr[jj][ii];
    }
}

// ---------------- persistent Sinkhorn + loss per pair ----------------------
__global__ void __launch_bounds__(NTHR, 1) sink_k(int pair) {
    __shared__ __align__(16) float ysm[NP];   // 16 KB staged x (fp32)
    __shared__ __align__(16) char  tsm[NP];   // 4 KB quantized x (int8)
    __shared__ float rmn[16], rmx[16], rsm[16];
    __shared__ float s_mv, s_sv, s_isv, s_sum;

    const int tid  = threadIdx.x;
    const int lane = tid & 31;
    const int wid  = tid >> 5;
    const int gw   = blockIdx.x * (NTHR / 32) + wid;   // 0..NWARP-1
    int bar = pair * TOTB;

    // ---- pre-pass: row sums of S and ST (dp4a with +1 bytes), u := 1 ----
    for (int vr = gw; vr < 2 * NP; vr += NWARP) {
        const char* row = (vr < NP ? g_S : g_ST) + (size_t)(vr & (NP - 1)) * NP;
        const uint4* p = (const uint4*)row + lane;
        int d = 0;
#pragma unroll
        for (int k = 0; k < 8; k++) {
            uint4 q = p[k * 32];
            d = __dp4a((int)q.x, 0x01010101, d);
            d = __dp4a((int)q.y, 0x01010101, d);
            d = __dp4a((int)q.z, 0x01010101, d);
            d = __dp4a((int)q.w, 0x01010101, d);
        }
        d = wsumi(d);
        if (lane == 0) (vr < NP ? g_rsS : g_rsT)[vr & (NP - 1)] = d;
    }
    {
        int gi = blockIdx.x * NTHR + tid;
        if (gi < NP) g_u[gi] = 1.0f;
    }
    bar++; gsync(bar);

    // ---- 200 half-iterations ----
    for (int half = 0; half < 2 * NITER; half++) {
        const int dir = half & 1;                 // 0: v = f(K^T u), 1: u = f(K v)
        const char* M  = dir ? g_S  : g_ST;
        const int*  rs = dir ? g_rsS : g_rsT;
        const float* x = dir ? g_v : g_u;
        float*       y = dir ? g_u : g_v;

        // stage x (fp32) via L2
        for (int i4 = tid; i4 < NP / 4; i4 += NTHR)
            ((float4*)ysm)[i4] = __ldcg((const float4*)x + i4);
        __syncthreads();

        // block reduce min/max/sum (fixed order -> deterministic, same in all blocks)
        float mn = 1e30f, mx = -1e30f, sm = 0.f;
        for (int j = tid; j < NP; j += NTHR) {
            float v = ysm[j];
            mn = fminf(mn, v); mx = fmaxf(mx, v); sm += v;
        }
#pragma unroll
        for (int o = 16; o > 0; o >>= 1) {
            mn = fminf(mn, __shfl_down_sync(0xffffffffu, mn, o));
            mx = fmaxf(mx, __shfl_down_sync(0xffffffffu, mx, o));
            sm += __shfl_down_sync(0xffffffffu, sm, o);
        }
        if (lane == 0) { rmn[wid] = mn; rmx[wid] = mx; rsm[wid] = sm; }
        __syncthreads();
        if (tid < 32) {
            float a = (tid < 16) ? rmn[tid] : 1e30f;
            float b = (tid < 16) ? rmx[tid] : -1e30f;
            float c = (tid < 16) ? rsm[tid] : 0.f;
#pragma unroll
            for (int o = 8; o > 0; o >>= 1) {
                a = fminf(a, __shfl_down_sync(0xffffffffu, a, o));
                b = fmaxf(b, __shfl_down_sync(0xffffffffu, b, o));
                c += __shfl_down_sync(0xffffffffu, c, o);
            }
            if (tid == 0) {
                float rg = b - a;
                s_mv = 0.5f * (a + b);
                s_sv = rg * (1.0f / 254.0f);
                s_isv = (rg > 1e-30f) ? (254.0f / rg) : 0.0f;
                s_sum = c;
            }
        }
        __syncthreads();
        const float mv = s_mv, sv = s_sv, isv = s_isv, sumv = s_sum;

        // quantize x -> int8 in smem
        for (int j = tid; j < NP; j += NTHR) {
            int t = __float2int_rn((ysm[j] - mv) * isv);
            t = max(-127, min(127, t));
            tsm[j] = (char)t;
        }
        __syncthreads();

        // dot: 2 rows per warp, dp4a int8 x int8 (exact)
        if (gw < NP / 2) {
            const int r0 = gw * 2, r1 = r0 + 1;
            const uint4* p0 = (const uint4*)(M + (size_t)r0 * NP) + lane;
            const uint4* p1 = (const uint4*)(M + (size_t)r1 * NP) + lane;
            int d0 = 0, d1 = 0;
#pragma unroll
            for (int k = 0; k < 8; k++) {
                uint4 a = p0[k * 32];
                uint4 b = p1[k * 32];
                int4 t4 = ((const int4*)tsm)[k * 32 + lane];
                d0 = __dp4a((int)a.x, t4.x, d0); d0 = __dp4a((int)a.y, t4.y, d0);
                d0 = __dp4a((int)a.z, t4.z, d0); d0 = __dp4a((int)a.w, t4.w, d0);
                d1 = __dp4a((int)b.x, t4.x, d1); d1 = __dp4a((int)b.y, t4.y, d1);
                d1 = __dp4a((int)b.z, t4.z, d1); d1 = __dp4a((int)b.w, t4.w, d1);
            }
            d0 = wsumi(d0);
            d1 = wsumi(d1);
            if (lane == 0) {
                float base = 64.0f * sumv;
                float kv0 = (mv * (float)rs[r0] + sv * (float)d0 + base) * (1.0f / 255.0f);
                float kv1 = (mv * (float)rs[r1] + sv * (float)d1 + base) * (1.0f / 255.0f);
                y[r0] = MUV / (kv0 + EPSV);
                y[r1] = MUV / (kv1 + EPSV);
            }
        }
        bar++; gsync(bar);
    }

    // ---- loss: sum_ij u_i * (S_ij+64)/255 * C_ij * v_j ----
    for (int i4 = tid; i4 < NP / 4; i4 += NTHR)
        ((float4*)ysm)[i4] = __ldcg((const float4*)g_v + i4);
    __syncthreads();

    float part = 0.f;
    if (gw < NP / 2) {
#pragma unroll 1
        for (int rr = 0; rr < 2; rr++) {
            int r = gw * 2 + rr;
            const uint4* ps = (const uint4*)(g_S + (size_t)r * NP) + lane;
            const uint4* pc = (const uint4*)((const char*)g_C + (size_t)r * NP * 2) + lane * 2;
            float s = 0.f;
#pragma unroll
            for (int k = 0; k < 8; k++) {
                uint4 qs  = ps[k * 32];
                uint4 qc0 = pc[k * 64];
                uint4 qc1 = pc[k * 64 + 1];
                const __half2* h0 = (const __half2*)&qc0;
                const __half2* h1 = (const __half2*)&qc1;
                int e = (lane + k * 32) * 16;
#pragma unroll
                for (int w = 0; w < 4; w++) {
                    int word = ((const int*)&qs)[w];
                    const __half2* hh = (w < 2) ? (h0 + 2 * w) : (h1 + 2 * (w - 2));
                    float2 c0 = __half22float2(hh[0]);
                    float2 c1 = __half22float2(hh[1]);
                    int s0 = (word << 24) >> 24;
                    int s1 = (word << 16) >> 24;
                    int s2 = (word << 8)  >> 24;
                    int s3 =  word        >> 24;
                    int eb = e + 4 * w;
                    s += (float)(s0 + 64) * c0.x * ysm[eb + 0];
                    s += (float)(s1 + 64) * c0.y * ysm[eb + 1];
                    s += (float)(s2 + 64) * c1.x * ysm[eb + 2];
                    s += (float)(s3 + 64) * c1.y * ysm[eb + 3];
                }
            }
            s = wsumf(s);
            if (lane == 0) part += s * (1.0f / 255.0f) * __ldcg(&g_u[r]);
        }
    }
    // block reduce part (fixed order)
    if (lane == 0) rsm[wid] = part;
    __syncthreads();
    if (tid == 0) {
        float b = 0.f;
#pragma unroll
        for (int q = 0; q < 16; q++) b += rsm[q];
        g_part[blockIdx.x] = b;
    }
    bar++; gsync(bar);
    if (blockIdx.x == 0 && tid == 0) {
        float t = 0.f;
        for (int i = 0; i < NBLK; i++) t += __ldcg((const float*)&g_part[i]);
        g_result += t;
    }
}

// ---------------- finalize + reset barrier state ---------------------------
__global__ void fin_k(float* out) {
    if (threadIdx.x == 0) {
        out[0] = g_result * (1.0f / 3.0f);
        g_gen = 0;
    }
    if (threadIdx.x < NBLK) g_flag[threadIdx.x * 32] = 0;
}

// ---------------- launch ---------------------------------------------------
extern "C" void kernel_launch(void* const* d_in, const int* in_sizes, int n_in,
                              void* d_out, int out_size) {
    const float* z0 = (const float*)d_in[0];
    const float* z1 = (const float*)d_in[1];
    const float* z2 = (const float*)d_in[2];
    float* out = (float*)d_out;

    norms_k<<<1536, 256>>>(z0, z1, z2);

    const float* Xs[3] = { z0, z0, z1 };
    const float* Ys[3] = { z1, z2, z2 };
    const int    xi[3] = { 0, 0, 1 };
    const int    yi[3] = { 1, 2, 2 };

    for (int p = 0; p < 3; p++) {
        gemm_expK_k<<<4096, 256>>>(Xs[p], Ys[p], xi[p], yi[p]);
        sink_k<<<NBLK, NTHR>>>(p);
    }
    fin_k<<<1, 256>>>(out);
}

// round 6
// speedup vs baseline: 1.4115x; 1.1053x over previous
#include <cuda_runtime.h>
#include <cuda_fp16.h>
#include <cstdint>

#define NP 4096
#define DI 128
#define REGINV 20.0f          // 1/0.05
#define MUV (1.0f/4096.0f)
#define EPSV 1e-8f
#define NITER 100
#define NBLK 128
#define NTHR 1024
#define NWARP (NBLK*(NTHR/32))   // 4096 == NP
#define TOTB 202                 // barriers per pair: 1 pre + 200 passes + 1 loss

// ---------------- device scratch (no allocations allowed) ----------------
__device__ char   g_S [(size_t)NP * NP];   // 16 MB  S[i][j] = round(255*K)-64
__device__ char   g_ST[(size_t)NP * NP];   // 16 MB  transpose
__device__ __half g_C [(size_t)NP * NP];   // 32 MB  clipped cost (loss only)
__device__ int    g_rsS[NP];               // row sums of S
__device__ int    g_rsT[NP];               // row sums of ST
__device__ float  g_u[NP];
__device__ float  g_v[NP];
__device__ float  g_norm[3][NP];
__device__ float  g_part[NBLK];
__device__ float  g_result;
__device__ volatile int g_flag[NBLK * 32]; // one 128B line per block

__device__ __forceinline__ float wsumf(float v) {
#pragma unroll
    for (int o = 16; o > 0; o >>= 1) v += __shfl_down_sync(0xffffffffu, v, o);
    return v;
}
__device__ __forceinline__ int wsumi(int v) {
#pragma unroll
    for (int o = 16; o > 0; o >>= 1) v += __shfl_down_sync(0xffffffffu, v, o);
    return v;
}

// ---------------- one-hop grid barrier (monotonic; reset by fin_k) --------
__device__ __forceinline__ void gsync(int bar) {
    __threadfence();                       // publish this block's stores
    __syncthreads();
    if (threadIdx.x == 0) g_flag[blockIdx.x * 32] = bar;
    if (threadIdx.x < NBLK) {
        while (g_flag[threadIdx.x * 32] < bar) { }
        __threadfence();                   // acquire
    }
    __syncthreads();
}

// ---------------- row squared norms (+ zero g_result) ---------------------
__global__ void norms_k(const float* __restrict__ z0, const float* __restrict__ z1,
                        const float* __restrict__ z2) {
    if (blockIdx.x == 0 && threadIdx.x == 0) g_result = 0.f;
    int w    = (blockIdx.x * blockDim.x + threadIdx.x) >> 5;
    int lane = threadIdx.x & 31;
    if (w >= 3 * NP) return;
    const float* z = (w < NP) ? z0 : (w < 2 * NP ? z1 : z2);
    int r = w & (NP - 1);
    float4 f = *(const float4*)(z + (size_t)r * DI + lane * 4);
    float s = f.x * f.x + f.y * f.y + f.z * f.z + f.w * f.w;
    s = wsumf(s);
    if (lane == 0) ((float*)g_norm)[w] = s;
}

// ---------------- GEMM -> S int8, ST int8, C fp16 -------------------------
__global__ void gemm_expK_k(const float* __restrict__ X, const float* __restrict__ Y,
                            int nxi, int nyi) {
    __shared__ __align__(16) float xs[32][68];   // pitch 272B: 16B-aligned rows
    __shared__ __align__(16) float ys[32][68];
    __shared__ __align__(16) char tr[64][80];

    const float* nx = g_norm[nxi];
    const float* ny = g_norm[nyi];

    int tid = threadIdx.x;
    int tx = tid & 15, ty = tid >> 4;
    int i0 = (blockIdx.x >> 6) << 6;
    int j0 = (blockIdx.x & 63) << 6;

    float acc[4][4];
#pragma unroll
    for (int a = 0; a < 4; a++)
#pragma unroll
        for (int b = 0; b < 4; b++) acc[a][b] = 0.f;

    for (int kk = 0; kk < DI; kk += 32) {
        __syncthreads();
#pragma unroll
        for (int idx = tid; idx < 2048; idx += 256) {
            int r = idx >> 5, k = idx & 31;
            xs[k][r] = X[(size_t)(i0 + r) * DI + kk + k];
            ys[k][r] = Y[(size_t)(j0 + r) * DI + kk + k];
        }
        __syncthreads();
#pragma unroll
        for (int k = 0; k < 32; k++) {
            float4 x4 = *(const float4*)&xs[k][ty * 4];   // LDS.128 (broadcast)
            float4 y4 = *(const float4*)&ys[k][tx * 4];   // LDS.128 (2-phase)
            float xr[4] = { x4.x, x4.y, x4.z, x4.w };
            float yr[4] = { y4.x, y4.y, y4.z, y4.w };
#pragma unroll
            for (int a = 0; a < 4; a++)
#pragma unroll
                for (int b = 0; b < 4; b++) acc[a][b] += xr[a] * yr[b];
        }
    }

#pragma unroll
    for (int a = 0; a < 4; a++) {
        int i = i0 + ty * 4 + a;
        float ni = nx[i];
        unsigned sq = 0;
        alignas(8) __half hc[4];
#pragma unroll
        for (int b = 0; b < 4; b++) {
            int j = j0 + tx * 4 + b;
            float c  = fmaxf(ni + ny[j] - 2.0f * acc[a][b], 0.0f);
            float kf = __expf(-REGINV * c);
            int q = __float2int_rn(kf * 255.f) - 64;
            q = min(q, 127);
            hc[b] = __float2half(c);
            char qc = (char)q;
            sq |= ((unsigned)(unsigned char)qc) << (8 * b);
            tr[tx * 4 + b][ty * 4 + a] = qc;
        }
        *(unsigned*)&g_S[(size_t)i * NP + j0 + tx * 4] = sq;
        *(uint2*)&g_C[(size_t)i * NP + j0 + tx * 4] = *(const uint2*)hc;
    }
    __syncthreads();
    {
        int jj = tid >> 2;
        int ii = (tid & 3) * 16;
        *(uint4*)&g_ST[(size_t)(j0 + jj) * NP + i0 + ii] = *(const uint4*)&tr[jj][ii];
    }
}

// ---------------- persistent Sinkhorn + loss per pair ----------------------
__global__ void __launch_bounds__(NTHR, 1) sink_k(int pair) {
    __shared__ __align__(16) float ysm[NP];   // 16 KB staged x (fp32)
    __shared__ __align__(16) char  tsm[NP];   // 4 KB quantized x (int8)
    __shared__ float rmn[32], rmx[32], rsm[32];
    __shared__ float s_mv, s_sv, s_isv, s_sum;

    const int tid  = threadIdx.x;
    const int lane = tid & 31;
    const int wid  = tid >> 5;
    const int gw   = blockIdx.x * (NTHR / 32) + wid;   // 0..4095 == row
    int bar = pair * TOTB;

    // ---- pre-pass: row sums of S and ST, u := 1 ----
#pragma unroll
    for (int h = 0; h < 2; h++) {
        int vr = gw + h * NWARP;     // rows 0..8191
        const char* row = (vr < NP ? g_S : g_ST) + (size_t)(vr & (NP - 1)) * NP;
        const uint4* p = (const uint4*)row + lane;
        int d = 0;
#pragma unroll
        for (int k = 0; k < 8; k++) {
            uint4 q = p[k * 32];
            d = __dp4a((int)q.x, 0x01010101, d);
            d = __dp4a((int)q.y, 0x01010101, d);
            d = __dp4a((int)q.z, 0x01010101, d);
            d = __dp4a((int)q.w, 0x01010101, d);
        }
        d = wsumi(d);
        if (lane == 0) (vr < NP ? g_rsS : g_rsT)[vr & (NP - 1)] = d;
    }
    {
        int gi = blockIdx.x * NTHR + tid;
        if (gi < NP) g_u[gi] = 1.0f;
    }
    bar++; gsync(bar);

    // ---- 200 half-iterations ----
    for (int half = 0; half < 2 * NITER; half++) {
        const int dir = half & 1;                 // 0: v = f(K^T u), 1: u = f(K v)
        const char* M  = dir ? g_S  : g_ST;
        const int*  rs = dir ? g_rsS : g_rsT;
        const float* x = dir ? g_v : g_u;
        float*       y = dir ? g_u : g_v;

        // stage x (fp32) via L2 — one float4 per thread
        ((float4*)ysm)[tid] = __ldcg((const float4*)x + tid);
        __syncthreads();

        // block reduce min/max/sum (fixed order -> deterministic, same everywhere)
        float mn = 1e30f, mx = -1e30f, sm = 0.f;
#pragma unroll
        for (int q = 0; q < 4; q++) {
            float v = ysm[tid + q * NTHR];
            mn = fminf(mn, v); mx = fmaxf(mx, v); sm += v;
        }
#pragma unroll
        for (int o = 16; o > 0; o >>= 1) {
            mn = fminf(mn, __shfl_down_sync(0xffffffffu, mn, o));
            mx = fmaxf(mx, __shfl_down_sync(0xffffffffu, mx, o));
            sm += __shfl_down_sync(0xffffffffu, sm, o);
        }
        if (lane == 0) { rmn[wid] = mn; rmx[wid] = mx; rsm[wid] = sm; }
        __syncthreads();
        if (tid < 32) {
            float a = rmn[tid], b = rmx[tid], c = rsm[tid];
#pragma unroll
            for (int o = 16; o > 0; o >>= 1) {
                a = fminf(a, __shfl_down_sync(0xffffffffu, a, o));
                b = fmaxf(b, __shfl_down_sync(0xffffffffu, b, o));
                c += __shfl_down_sync(0xffffffffu, c, o);
            }
            if (tid == 0) {
                float rg = b - a;
                s_mv = 0.5f * (a + b);
                s_sv = rg * (1.0f / 254.0f);
                s_isv = (rg > 1e-30f) ? (254.0f / rg) : 0.0f;
                s_sum = c;
            }
        }
        __syncthreads();
        const float mv = s_mv, sv = s_sv, isv = s_isv, sumv = s_sum;

        // quantize x -> int8 in smem (4 per thread)
#pragma unroll
        for (int q = 0; q < 4; q++) {
            int j = tid + q * NTHR;
            int t = __float2int_rn((ysm[j] - mv) * isv);
            tsm[j] = (char)max(-127, min(127, t));
        }
        __syncthreads();

        // dot: one row per warp, dp4a int8 x int8 (exact), MLP-4 batches
        {
            const uint4* p = (const uint4*)(M + (size_t)gw * NP) + lane;
            int d = 0;
#pragma unroll
            for (int t = 0; t < 8; t += 4) {
                uint4 a0 = p[(t + 0) * 32];
                uint4 a1 = p[(t + 1) * 32];
                uint4 a2 = p[(t + 2) * 32];
                uint4 a3 = p[(t + 3) * 32];
                int4 t0 = ((const int4*)tsm)[(t + 0) * 32 + lane];
                int4 t1 = ((const int4*)tsm)[(t + 1) * 32 + lane];
                int4 t2 = ((const int4*)tsm)[(t + 2) * 32 + lane];
                int4 t3 = ((const int4*)tsm)[(t + 3) * 32 + lane];
                d = __dp4a((int)a0.x, t0.x, d); d = __dp4a((int)a0.y, t0.y, d);
                d = __dp4a((int)a0.z, t0.z, d); d = __dp4a((int)a0.w, t0.w, d);
                d = __dp4a((int)a1.x, t1.x, d); d = __dp4a((int)a1.y, t1.y, d);
                d = __dp4a((int)a1.z, t1.z, d); d = __dp4a((int)a1.w, t1.w, d);
                d = __dp4a((int)a2.x, t2.x, d); d = __dp4a((int)a2.y, t2.y, d);
                d = __dp4a((int)a2.z, t2.z, d); d = __dp4a((int)a2.w, t2.w, d);
                d = __dp4a((int)a3.x, t3.x, d); d = __dp4a((int)a3.y, t3.y, d);
                d = __dp4a((int)a3.z, t3.z, d); d = __dp4a((int)a3.w, t3.w, d);
            }
            d = wsumi(d);
            if (lane == 0) {
                float kv = (mv * (float)rs[gw] + sv * (float)d + 64.0f * sumv) * (1.0f / 255.0f);
                y[gw] = MUV / (kv + EPSV);
            }
        }
        bar++; gsync(bar);
    }

    // ---- loss: sum_ij u_i * (S_ij+64)/255 * C_ij * v_j ----
    ((float4*)ysm)[tid] = __ldcg((const float4*)g_v + tid);
    __syncthreads();

    float part;
    {
        const int r = gw;
        const uint4* ps = (const uint4*)(g_S + (size_t)r * NP) + lane;
        const uint4* pc = (const uint4*)((const char*)g_C + (size_t)r * NP * 2) + lane * 2;
        float s = 0.f;
#pragma unroll
        for (int k = 0; k < 8; k++) {
            uint4 qs  = ps[k * 32];
            uint4 qc0 = pc[k * 64];
            uint4 qc1 = pc[k * 64 + 1];
            const __half2* h0 = (const __half2*)&qc0;
            const __half2* h1 = (const __half2*)&qc1;
            int e = (lane + k * 32) * 16;
#pragma unroll
            for (int w = 0; w < 4; w++) {
                int word = ((const int*)&qs)[w];
                const __half2* hh = (w < 2) ? (h0 + 2 * w) : (h1 + 2 * (w - 2));
                float2 c0 = __half22float2(hh[0]);
                float2 c1 = __half22float2(hh[1]);
                int s0 = (word << 24) >> 24;
                int s1 = (word << 16) >> 24;
                int s2 = (word << 8)  >> 24;
                int s3 =  word        >> 24;
                int eb = e + 4 * w;
                s += (float)(s0 + 64) * c0.x * ysm[eb + 0];
                s += (float)(s1 + 64) * c0.y * ysm[eb + 1];
                s += (float)(s2 + 64) * c1.x * ysm[eb + 2];
                s += (float)(s3 + 64) * c1.y * ysm[eb + 3];
            }
        }
        s = wsumf(s);
        part = s * (1.0f / 255.0f);
    }
    if (lane == 0) rsm[wid] = part * __ldcg(&g_u[gw]);
    __syncthreads();
    if (tid == 0) {
        float b = 0.f;
#pragma unroll
        for (int q = 0; q < 32; q++) b += rsm[q];
        g_part[blockIdx.x] = b;
    }
    bar++; gsync(bar);
    if (blockIdx.x == 0 && tid == 0) {
        float t = 0.f;
        for (int i = 0; i < NBLK; i++) t += __ldcg((const float*)&g_part[i]);
        g_result += t;
    }
}

// ---------------- finalize + reset barrier state ---------------------------
__global__ void fin_k(float* out) {
    if (threadIdx.x == 0) out[0] = g_result * (1.0f / 3.0f);
    if (threadIdx.x < NBLK) g_flag[threadIdx.x * 32] = 0;
}

// ---------------- launch ---------------------------------------------------
extern "C" void kernel_launch(void* const* d_in, const int* in_sizes, int n_in,
                              void* d_out, int out_size) {
    const float* z0 = (const float*)d_in[0];
    const float* z1 = (const float*)d_in[1];
    const float* z2 = (const float*)d_in[2];
    float* out = (float*)d_out;

    norms_k<<<1536, 256>>>(z0, z1, z2);

    const float* Xs[3] = { z0, z0, z1 };
    const float* Ys[3] = { z1, z2, z2 };
    const int    xi[3] = { 0, 0, 1 };
    const int    yi[3] = { 1, 2, 2 };

    for (int p = 0; p < 3; p++) {
        gemm_expK_k<<<4096, 256>>>(Xs[p], Ys[p], xi[p], yi[p]);
        sink_k<<<NBLK, NTHR>>>(p);
    }
    fin_k<<<1, 256>>>(out);
}

// round 7
// speedup vs baseline: 1.5541x; 1.1010x over previous
#include <cuda_runtime.h>
#include <cuda_fp16.h>
#include <cstdint>

#define NP 4096
#define DI 128
#define REGINV 20.0f          // 1/0.05
#define MUV (1.0f/4096.0f)
#define EPSV 1e-8f
#define NITER 100
#define NBLK 128
#define NTHR 1024
#define NWARP (NBLK*(NTHR/32))   // 4096 == NP
#define TOTB 202                 // barriers per pair: 1 pre + 200 passes + 1 loss

// ---------------- device scratch (no allocations allowed) ----------------
__device__ char   g_S [(size_t)NP * NP];   // 16 MB  S[i][j] = round(255*K)-64
__device__ char   g_ST[(size_t)NP * NP];   // 16 MB  transpose
__device__ __half g_C [(size_t)NP * NP];   // 32 MB  clipped cost (loss only)
__device__ int    g_rsS[NP];               // row sums of S
__device__ int    g_rsT[NP];               // row sums of ST
__device__ float  g_u[NP];
__device__ float  g_v[NP];
__device__ float  g_norm[3][NP];
__device__ float  g_part[NBLK];
__device__ float4 g_bstat[NBLK];           // per-block (mn, mx, sum) of its 32 y values
__device__ float  g_result;
__device__ volatile int g_flag[NBLK * 32]; // one 128B line per block

__device__ __forceinline__ float wsumf(float v) {
#pragma unroll
    for (int o = 16; o > 0; o >>= 1) v += __shfl_down_sync(0xffffffffu, v, o);
    return v;
}
__device__ __forceinline__ int wsumi(int v) {
#pragma unroll
    for (int o = 16; o > 0; o >>= 1) v += __shfl_down_sync(0xffffffffu, v, o);
    return v;
}

// ---------------- one-hop grid barrier (monotonic; reset by fin_k) --------
__device__ __forceinline__ void gsync(int bar) {
    __threadfence();                       // publish this block's stores
    __syncthreads();
    if (threadIdx.x == 0) g_flag[blockIdx.x * 32] = bar;
    if (threadIdx.x < NBLK) {
        while (g_flag[threadIdx.x * 32] < bar) { }
        __threadfence();                   // acquire
    }
    __syncthreads();
}

// ---------------- row squared norms (+ zero g_result) ---------------------
__global__ void norms_k(const float* __restrict__ z0, const float* __restrict__ z1,
                        const float* __restrict__ z2) {
    if (blockIdx.x == 0 && threadIdx.x == 0) g_result = 0.f;
    int w    = (blockIdx.x * blockDim.x + threadIdx.x) >> 5;
    int lane = threadIdx.x & 31;
    if (w >= 3 * NP) return;
    const float* z = (w < NP) ? z0 : (w < 2 * NP ? z1 : z2);
    int r = w & (NP - 1);
    float4 f = *(const float4*)(z + (size_t)r * DI + lane * 4);
    float s = f.x * f.x + f.y * f.y + f.z * f.z + f.w * f.w;
    s = wsumf(s);
    if (lane == 0) ((float*)g_norm)[w] = s;
}

// ---------------- GEMM (128x128 tile, 8x8/thread) -> S, ST, C -------------
struct GSmem {
    union {
        struct { float xs[16][132]; float ys[16][132]; } l;
        char tr[128][144];
    };
};

__global__ void __launch_bounds__(256, 2) gemm_expK_k(
        const float* __restrict__ X, const float* __restrict__ Y,
        int nxi, int nyi) {
    __shared__ __align__(16) GSmem sm;

    const float* nx = g_norm[nxi];
    const float* ny = g_norm[nyi];

    int tid = threadIdx.x;
    int tx = tid & 15, ty = tid >> 4;
    int i0 = (blockIdx.x >> 5) << 7;
    int j0 = (blockIdx.x & 31) << 7;

    float acc[8][8];
#pragma unroll
    for (int a = 0; a < 8; a++)
#pragma unroll
        for (int b = 0; b < 8; b++) acc[a][b] = 0.f;

    for (int kk = 0; kk < DI; kk += 16) {
        __syncthreads();
#pragma unroll
        for (int q = 0; q < 2; q++) {
            int f = tid + q * 256;
            int r = f >> 2;
            int kq = (f & 3) * 4;
            float4 xv = *(const float4*)(X + (size_t)(i0 + r) * DI + kk + kq);
            float4 yv = *(const float4*)(Y + (size_t)(j0 + r) * DI + kk + kq);
            sm.l.xs[kq + 0][r] = xv.x; sm.l.xs[kq + 1][r] = xv.y;
            sm.l.xs[kq + 2][r] = xv.z; sm.l.xs[kq + 3][r] = xv.w;
            sm.l.ys[kq + 0][r] = yv.x; sm.l.ys[kq + 1][r] = yv.y;
            sm.l.ys[kq + 2][r] = yv.z; sm.l.ys[kq + 3][r] = yv.w;
        }
        __syncthreads();
#pragma unroll 4
        for (int k = 0; k < 16; k++) {
            float4 xa = *(const float4*)&sm.l.xs[k][ty * 4];
            float4 xb = *(const float4*)&sm.l.xs[k][64 + ty * 4];
            float4 ya = *(const float4*)&sm.l.ys[k][tx * 4];
            float4 yb = *(const float4*)&sm.l.ys[k][64 + tx * 4];
            float xr[8] = { xa.x, xa.y, xa.z, xa.w, xb.x, xb.y, xb.z, xb.w };
            float yr[8] = { ya.x, ya.y, ya.z, ya.w, yb.x, yb.y, yb.z, yb.w };
#pragma unroll
            for (int a = 0; a < 8; a++)
#pragma unroll
                for (int b = 0; b < 8; b++) acc[a][b] += xr[a] * yr[b];
        }
    }
    __syncthreads();   // xs/ys dead; tr may now be written

    // epilogue: rows a<4 -> ty*4+a, a>=4 -> 64+ty*4+(a-4); cols likewise with tx
#pragma unroll
    for (int a = 0; a < 8; a++) {
        int il = (a < 4) ? (ty * 4 + a) : (64 + ty * 4 + a - 4);
        int i = i0 + il;
        float ni = __ldg(nx + i);
#pragma unroll
        for (int p = 0; p < 2; p++) {
            int jl0 = p * 64 + tx * 4;
            unsigned sq = 0;
            alignas(8) __half hc[4];
#pragma unroll
            for (int e = 0; e < 4; e++) {
                int j = j0 + jl0 + e;
                float c  = fmaxf(ni + __ldg(ny + j) - 2.0f * acc[a][p * 4 + e], 0.0f);
                float kf = __expf(-REGINV * c);
                int q = __float2int_rn(kf * 255.f) - 64;
                q = min(q, 127);
                hc[e] = __float2half(c);
                char qc = (char)q;
                sq |= ((unsigned)(unsigned char)qc) << (8 * e);
                sm.tr[jl0 + e][il] = qc;
            }
            *(unsigned*)&g_S[(size_t)i * NP + j0 + jl0] = sq;
            *(uint2*)&g_C[(size_t)i * NP + j0 + jl0] = *(const uint2*)hc;
        }
    }
    __syncthreads();
    // ST writeout: 128 rows x 128 B; thread t: row t>>1, half (t&1)*64, 4 x uint4
    {
        int jj = tid >> 1;
        int ii = (tid & 1) * 64;
#pragma unroll
        for (int q = 0; q < 4; q++)
            *(uint4*)&g_ST[(size_t)(j0 + jj) * NP + i0 + ii + q * 16] =
                *(const uint4*)&sm.tr[jj][ii + q * 16];
    }
}

// ---------------- persistent Sinkhorn + loss per pair ----------------------
__global__ void __launch_bounds__(NTHR, 1) sink_k(int pair) {
    __shared__ __align__(16) float ysm[NP];   // 16 KB (loss stage only)
    __shared__ __align__(16) char  tsm[NP];   // 4 KB quantized x
    __shared__ float yvs[32];                 // this block's 32 y values
    __shared__ float rsm[32];
    __shared__ float s_mv, s_sv, s_isv, s_sum;

    const int tid  = threadIdx.x;
    const int lane = tid & 31;
    const int wid  = tid >> 5;
    const int gw   = blockIdx.x * (NTHR / 32) + wid;   // 0..4095 == row
    int bar = pair * TOTB;

    // ---- pre-pass: row sums of S and ST, u := 1, bstat for u=1 ----
#pragma unroll
    for (int h = 0; h < 2; h++) {
        int vr = gw + h * NWARP;
        const char* row = (vr < NP ? g_S : g_ST) + (size_t)(vr & (NP - 1)) * NP;
        const uint4* p = (const uint4*)row + lane;
        int d = 0;
#pragma unroll
        for (int k = 0; k < 8; k++) {
            uint4 q = p[k * 32];
            d = __dp4a((int)q.x, 0x01010101, d);
            d = __dp4a((int)q.y, 0x01010101, d);
            d = __dp4a((int)q.z, 0x01010101, d);
            d = __dp4a((int)q.w, 0x01010101, d);
        }
        d = wsumi(d);
        if (lane == 0) (vr < NP ? g_rsS : g_rsT)[vr & (NP - 1)] = d;
    }
    {
        int gi = blockIdx.x * NTHR + tid;
        if (gi < NP) g_u[gi] = 1.0f;
    }
    if (tid == 0) g_bstat[blockIdx.x] = make_float4(1.0f, 1.0f, 32.0f, 0.0f);
    bar++; gsync(bar);

    // ---- 200 half-iterations ----
    for (int half = 0; half < 2 * NITER; half++) {
        const int dir = half & 1;                 // 0: v = f(K^T u), 1: u = f(K v)
        const char* M  = dir ? g_S  : g_ST;
        const int*  rs = dir ? g_rsS : g_rsT;
        const float* x = dir ? g_v : g_u;
        float*       y = dir ? g_u : g_v;

        // 1) global stats from 128 block-stats (fixed order -> identical everywhere)
        if (tid < 32) {
            float mn = 1e30f, mx = -1e30f, sm = 0.f;
#pragma unroll
            for (int q = 0; q < 4; q++) {
                float4 b = __ldcg(&g_bstat[tid + q * 32]);
                mn = fminf(mn, b.x); mx = fmaxf(mx, b.y); sm += b.z;
            }
#pragma unroll
            for (int o = 16; o > 0; o >>= 1) {
                mn = fminf(mn, __shfl_down_sync(0xffffffffu, mn, o));
                mx = fmaxf(mx, __shfl_down_sync(0xffffffffu, mx, o));
                sm += __shfl_down_sync(0xffffffffu, sm, o);
            }
            if (tid == 0) {
                float rg = mx - mn;
                s_mv = 0.5f * (mn + mx);
                s_sv = rg * (1.0f / 254.0f);
                s_isv = (rg > 1e-30f) ? (254.0f / rg) : 0.0f;
                s_sum = sm;
            }
        }
        __syncthreads();
        const float mv = s_mv, sv = s_sv, isv = s_isv, sumv = s_sum;

        // 2) quantize x directly from global (one float4 per thread)
        {
            float4 xv = __ldcg((const float4*)x + tid);
            int t0 = max(-127, min(127, __float2int_rn((xv.x - mv) * isv)));
            int t1 = max(-127, min(127, __float2int_rn((xv.y - mv) * isv)));
            int t2 = max(-127, min(127, __float2int_rn((xv.z - mv) * isv)));
            int t3 = max(-127, min(127, __float2int_rn((xv.w - mv) * isv)));
            ((char4*)tsm)[tid] = make_char4((char)t0, (char)t1, (char)t2, (char)t3);
        }
        __syncthreads();

        // 3) dot: one row per warp, dp4a int8 x int8 (exact), MLP-4 batches
        {
            const uint4* p = (const uint4*)(M + (size_t)gw * NP) + lane;
            int d = 0;
#pragma unroll
            for (int t = 0; t < 8; t += 4) {
                uint4 a0 = p[(t + 0) * 32];
                uint4 a1 = p[(t + 1) * 32];
                uint4 a2 = p[(t + 2) * 32];
                uint4 a3 = p[(t + 3) * 32];
                int4 t0 = ((const int4*)tsm)[(t + 0) * 32 + lane];
                int4 t1 = ((const int4*)tsm)[(t + 1) * 32 + lane];
                int4 t2 = ((const int4*)tsm)[(t + 2) * 32 + lane];
                int4 t3 = ((const int4*)tsm)[(t + 3) * 32 + lane];
                d = __dp4a((int)a0.x, t0.x, d); d = __dp4a((int)a0.y, t0.y, d);
                d = __dp4a((int)a0.z, t0.z, d); d = __dp4a((int)a0.w, t0.w, d);
                d = __dp4a((int)a1.x, t1.x, d); d = __dp4a((int)a1.y, t1.y, d);
                d = __dp4a((int)a1.z, t1.z, d); d = __dp4a((int)a1.w, t1.w, d);
                d = __dp4a((int)a2.x, t2.x, d); d = __dp4a((int)a2.y, t2.y, d);
                d = __dp4a((int)a2.z, t2.z, d); d = __dp4a((int)a2.w, t2.w, d);
                d = __dp4a((int)a3.x, t3.x, d); d = __dp4a((int)a3.y, t3.y, d);
                d = __dp4a((int)a3.z, t3.z, d); d = __dp4a((int)a3.w, t3.w, d);
            }
            d = wsumi(d);
            if (lane == 0) {
                float kv = (mv * (float)rs[gw] + sv * (float)d + 64.0f * sumv) * (1.0f / 255.0f);
                float yv = MUV / (kv + EPSV);
                y[gw] = yv;
                yvs[wid] = yv;
            }
        }
        __syncthreads();

        // 4) publish this block's y-stats, then barrier
        if (tid < 32) {
            float v = yvs[lane];
            float mn = v, mx = v, sm = v;
#pragma unroll
            for (int o = 16; o > 0; o >>= 1) {
                mn = fminf(mn, __shfl_down_sync(0xffffffffu, mn, o));
                mx = fmaxf(mx, __shfl_down_sync(0xffffffffu, mx, o));
                sm += __shfl_down_sync(0xffffffffu, sm, o);
            }
            if (tid == 0) g_bstat[blockIdx.x] = make_float4(mn, mx, sm, 0.f);
        }
        bar++; gsync(bar);
    }

    // ---- loss: sum_ij u_i * (S_ij+64)/255 * C_ij * v_j ----
    ((float4*)ysm)[tid] = __ldcg((const float4*)g_v + tid);
    __syncthreads();

    float part;
    {
        const int r = gw;
        const uint4* ps = (const uint4*)(g_S + (size_t)r * NP) + lane;
        const uint4* pc = (const uint4*)((const char*)g_C + (size_t)r * NP * 2) + lane * 2;
        float s = 0.f;
#pragma unroll
        for (int k = 0; k < 8; k++) {
            uint4 qs  = ps[k * 32];
            uint4 qc0 = pc[k * 64];
            uint4 qc1 = pc[k * 64 + 1];
            const __half2* h0 = (const __half2*)&qc0;
            const __half2* h1 = (const __half2*)&qc1;
            int e = (lane + k * 32) * 16;
#pragma unroll
            for (int w = 0; w < 4; w++) {
                int word = ((const int*)&qs)[w];
                const __half2* hh = (w < 2) ? (h0 + 2 * w) : (h1 + 2 * (w - 2));
                float2 c0 = __half22float2(hh[0]);
                float2 c1 = __half22float2(hh[1]);
                int s0 = (word << 24) >> 24;
                int s1 = (word << 16) >> 24;
                int s2 = (word << 8)  >> 24;
                int s3 =  word        >> 24;
                int eb = e + 4 * w;
                s += (float)(s0 + 64) * c0.x * ysm[eb + 0];
                s += (float)(s1 + 64) * c0.y * ysm[eb + 1];
                s += (float)(s2 + 64) * c1.x * ysm[eb + 2];
                s += (float)(s3 + 64) * c1.y * ysm[eb + 3];
            }
        }
        s = wsumf(s);
        part = s * (1.0f / 255.0f);
    }
    if (lane == 0) rsm[wid] = part * __ldcg(&g_u[gw]);
    __syncthreads();
    if (tid == 0) {
        float b = 0.f;
#pragma unroll
        for (int q = 0; q < 32; q++) b += rsm[q];
        g_part[blockIdx.x] = b;
    }
    bar++; gsync(bar);
    if (blockIdx.x == 0 && tid == 0) {
        float t = 0.f;
        for (int i = 0; i < NBLK; i++) t += __ldcg((const float*)&g_part[i]);
        g_result += t;
    }
}

// ---------------- finalize + reset barrier state ---------------------------
__global__ void fin_k(float* out) {
    if (threadIdx.x == 0) out[0] = g_result * (1.0f / 3.0f);
    if (threadIdx.x < NBLK) g_flag[threadIdx.x * 32] = 0;
}

// ---------------- launch ---------------------------------------------------
extern "C" void kernel_launch(void* const* d_in, const int* in_sizes, int n_in,
                              void* d_out, int out_size) {
    const float* z0 = (const float*)d_in[0];
    const float* z1 = (const float*)d_in[1];
    const float* z2 = (const float*)d_in[2];
    float* out = (float*)d_out;

    norms_k<<<1536, 256>>>(z0, z1, z2);

    const float* Xs[3] = { z0, z0, z1 };
    const float* Ys[3] = { z1, z2, z2 };
    const int    xi[3] = { 0, 0, 1 };
    const int    yi[3] = { 1, 2, 2 };

    for (int p = 0; p < 3; p++) {
        gemm_expK_k<<<1024, 256>>>(Xs[p], Ys[p], xi[p], yi[p]);
        sink_k<<<NBLK, NTHR>>>(p);
    }
    fin_k<<<1, 256>>>(out);
}

// round 8
// speedup vs baseline: 1.5664x; 1.0080x over previous
#include <cuda_runtime.h>
#include <cuda_fp16.h>
#include <cstdint>

#define NP 4096
#define DI 128
#define REGINV 20.0f          // 1/0.05
#define MUV (1.0f/4096.0f)
#define EPSV 1e-8f
#define NITER 100
#define NBLK 128
#define NTHR 1024
#define NWARP (NBLK*(NTHR/32))   // 4096 == NP
#define TOTB 202                 // barriers per pair: 1 pre + 200 passes + 1 loss

// ---------------- device scratch (no allocations allowed) ----------------
__device__ char   g_S [(size_t)NP * NP];   // 16 MB  S[i][j] = round(255*K)-64
__device__ char   g_ST[(size_t)NP * NP];   // 16 MB  transpose
__device__ __half g_C [(size_t)NP * NP];   // 32 MB  clipped cost (loss only)
__device__ int    g_rsS[NP];               // row sums of S
__device__ int    g_rsT[NP];               // row sums of ST
__device__ float  g_u[NP];
__device__ float  g_v[NP];
__device__ float  g_norm[3][NP];
__device__ float  g_part[NBLK];
__device__ float4 g_bstat[NBLK];           // per-block (mn, mx, sum) of its 32 y values
__device__ float  g_result;
__device__ int    g_flag[NBLK * 32];       // one 128B line per block

__device__ __forceinline__ float wsumf(float v) {
#pragma unroll
    for (int o = 16; o > 0; o >>= 1) v += __shfl_down_sync(0xffffffffu, v, o);
    return v;
}
__device__ __forceinline__ int wsumi(int v) {
#pragma unroll
    for (int o = 16; o > 0; o >>= 1) v += __shfl_down_sync(0xffffffffu, v, o);
    return v;
}

// ---------------- one-hop grid barrier, release/acquire -------------------
__device__ __forceinline__ void gsync(int bar) {
    __syncthreads();
    if (threadIdx.x == 0) {
        __threadfence();   // make the whole block's prior writes gpu-visible
        asm volatile("st.release.gpu.global.b32 [%0], %1;"
                     :: "l"(&g_flag[blockIdx.x * 32]), "r"(bar) : "memory");
    }
    if (threadIdx.x < NBLK) {
        int v;
        do {
            asm volatile("ld.acquire.gpu.global.b32 %0, [%1];"
                         : "=r"(v) : "l"(&g_flag[threadIdx.x * 32]) : "memory");
        } while (v < bar);
    }
    __syncthreads();
}

// ---------------- row squared norms (+ zero g_result) ---------------------
__global__ void norms_k(const float* __restrict__ z0, const float* __restrict__ z1,
                        const float* __restrict__ z2) {
    if (blockIdx.x == 0 && threadIdx.x == 0) g_result = 0.f;
    int w    = (blockIdx.x * blockDim.x + threadIdx.x) >> 5;
    int lane = threadIdx.x & 31;
    if (w >= 3 * NP) return;
    const float* z = (w < NP) ? z0 : (w < 2 * NP ? z1 : z2);
    int r = w & (NP - 1);
    float4 f = *(const float4*)(z + (size_t)r * DI + lane * 4);
    float s = f.x * f.x + f.y * f.y + f.z * f.z + f.w * f.w;
    s = wsumf(s);
    if (lane == 0) ((float*)g_norm)[w] = s;
}

// ---------------- GEMM (128x128 tile, 8x8/thread) -> S, ST, C -------------
struct GSmem {
    union {
        struct { float xs[16][132]; float ys[16][132]; } l;
        char tr[128][144];
    };
};

__global__ void __launch_bounds__(256, 2) gemm_expK_k(
        const float* __restrict__ X, const float* __restrict__ Y,
        int nxi, int nyi) {
    __shared__ __align__(16) GSmem sm;

    const float* nx = g_norm[nxi];
    const float* ny = g_norm[nyi];

    int tid = threadIdx.x;
    int tx = tid & 15, ty = tid >> 4;
    int i0 = (blockIdx.x >> 5) << 7;
    int j0 = (blockIdx.x & 31) << 7;

    float acc[8][8];
#pragma unroll
    for (int a = 0; a < 8; a++)
#pragma unroll
        for (int b = 0; b < 8; b++) acc[a][b] = 0.f;

    for (int kk = 0; kk < DI; kk += 16) {
        __syncthreads();
#pragma unroll
        for (int q = 0; q < 2; q++) {
            int f = tid + q * 256;
            int r = f >> 2;
            int kq = (f & 3) * 4;
            float4 xv = *(const float4*)(X + (size_t)(i0 + r) * DI + kk + kq);
            float4 yv = *(const float4*)(Y + (size_t)(j0 + r) * DI + kk + kq);
            sm.l.xs[kq + 0][r] = xv.x; sm.l.xs[kq + 1][r] = xv.y;
            sm.l.xs[kq + 2][r] = xv.z; sm.l.xs[kq + 3][r] = xv.w;
            sm.l.ys[kq + 0][r] = yv.x; sm.l.ys[kq + 1][r] = yv.y;
            sm.l.ys[kq + 2][r] = yv.z; sm.l.ys[kq + 3][r] = yv.w;
        }
        __syncthreads();
#pragma unroll 4
        for (int k = 0; k < 16; k++) {
            float4 xa = *(const float4*)&sm.l.xs[k][ty * 4];
            float4 xb = *(const float4*)&sm.l.xs[k][64 + ty * 4];
            float4 ya = *(const float4*)&sm.l.ys[k][tx * 4];
            float4 yb = *(const float4*)&sm.l.ys[k][64 + tx * 4];
            float xr[8] = { xa.x, xa.y, xa.z, xa.w, xb.x, xb.y, xb.z, xb.w };
            float yr[8] = { ya.x, ya.y, ya.z, ya.w, yb.x, yb.y, yb.z, yb.w };
#pragma unroll
            for (int a = 0; a < 8; a++)
#pragma unroll
                for (int b = 0; b < 8; b++) acc[a][b] += xr[a] * yr[b];
        }
    }
    __syncthreads();   // xs/ys dead; tr may now be written

#pragma unroll
    for (int a = 0; a < 8; a++) {
        int il = (a < 4) ? (ty * 4 + a) : (64 + ty * 4 + a - 4);
        int i = i0 + il;
        float ni = __ldg(nx + i);
#pragma unroll
        for (int p = 0; p < 2; p++) {
            int jl0 = p * 64 + tx * 4;
            unsigned sq = 0;
            alignas(8) __half hc[4];
#pragma unroll
            for (int e = 0; e < 4; e++) {
                int j = j0 + jl0 + e;
                float c  = fmaxf(ni + __ldg(ny + j) - 2.0f * acc[a][p * 4 + e], 0.0f);
                float kf = __expf(-REGINV * c);
                int q = __float2int_rn(kf * 255.f) - 64;
                q = min(q, 127);
                hc[e] = __float2half(c);
                char qc = (char)q;
                sq |= ((unsigned)(unsigned char)qc) << (8 * e);
                sm.tr[jl0 + e][il] = qc;
            }
            *(unsigned*)&g_S[(size_t)i * NP + j0 + jl0] = sq;
            *(uint2*)&g_C[(size_t)i * NP + j0 + jl0] = *(const uint2*)hc;
        }
    }
    __syncthreads();
    {
        int jj = tid >> 1;
        int ii = (tid & 1) * 64;
#pragma unroll
        for (int q = 0; q < 4; q++)
            *(uint4*)&g_ST[(size_t)(j0 + jj) * NP + i0 + ii + q * 16] =
                *(const uint4*)&sm.tr[jj][ii + q * 16];
    }
}

// ---------------- persistent Sinkhorn + loss per pair ----------------------
__global__ void __launch_bounds__(NTHR, 1) sink_k(int pair) {
    __shared__ __align__(16) float ysm[NP];   // 16 KB (loss stage only)
    __shared__ __align__(16) char  tsm[NP];   // 4 KB quantized x
    __shared__ float yvs[32];                 // this block's 32 y values
    __shared__ float rsm[32];
    __shared__ float s_mv, s_sv, s_isv, s_sum;

    const int tid  = threadIdx.x;
    const int lane = tid & 31;
    const int wid  = tid >> 5;
    const int gw   = blockIdx.x * (NTHR / 32) + wid;   // 0..4095 == row
    int bar = pair * TOTB;

    // ---- pre-pass: row sums of S and ST, u := 1, bstat for u=1 ----
#pragma unroll
    for (int h = 0; h < 2; h++) {
        int vr = gw + h * NWARP;
        const char* row = (vr < NP ? g_S : g_ST) + (size_t)(vr & (NP - 1)) * NP;
        const uint4* p = (const uint4*)row + lane;
        int d = 0;
#pragma unroll
        for (int k = 0; k < 8; k++) {
            uint4 q = p[k * 32];
            d = __dp4a((int)q.x, 0x01010101, d);
            d = __dp4a((int)q.y, 0x01010101, d);
            d = __dp4a((int)q.z, 0x01010101, d);
            d = __dp4a((int)q.w, 0x01010101, d);
        }
        d = wsumi(d);
        if (lane == 0) (vr < NP ? g_rsS : g_rsT)[vr & (NP - 1)] = d;
    }
    {
        int gi = blockIdx.x * NTHR + tid;
        if (gi < NP) g_u[gi] = 1.0f;
    }
    if (tid == 0) g_bstat[blockIdx.x] = make_float4(1.0f, 1.0f, 32.0f, 0.0f);

    // prefetch first half of the first pass's row (dir=0 -> M = g_ST)
    const uint4* prow = (const uint4*)(g_ST + (size_t)gw * NP) + lane;
    uint4 ph0 = prow[0 * 32];
    uint4 ph1 = prow[1 * 32];
    uint4 ph2 = prow[2 * 32];
    uint4 ph3 = prow[3 * 32];

    bar++; gsync(bar);

    // ---- 200 half-iterations ----
    for (int half = 0; half < 2 * NITER; half++) {
        const int dir = half & 1;                 // 0: v = f(K^T u), 1: u = f(K v)
        const int*  rs = dir ? g_rsS : g_rsT;
        const float* x = dir ? g_v : g_u;
        float*       y = dir ? g_u : g_v;

        // 0) issue second-half row loads immediately (hidden behind stats+quantize)
        uint4 ph4 = prow[4 * 32];
        uint4 ph5 = prow[5 * 32];
        uint4 ph6 = prow[6 * 32];
        uint4 ph7 = prow[7 * 32];

        // 1) global stats from 128 block-stats (fixed order -> identical everywhere)
        if (tid < 32) {
            float mn = 1e30f, mx = -1e30f, sm = 0.f;
#pragma unroll
            for (int q = 0; q < 4; q++) {
                float4 b = __ldcg(&g_bstat[tid + q * 32]);
                mn = fminf(mn, b.x); mx = fmaxf(mx, b.y); sm += b.z;
            }
#pragma unroll
            for (int o = 16; o > 0; o >>= 1) {
                mn = fminf(mn, __shfl_down_sync(0xffffffffu, mn, o));
                mx = fmaxf(mx, __shfl_down_sync(0xffffffffu, mx, o));
                sm += __shfl_down_sync(0xffffffffu, sm, o);
            }
            if (tid == 0) {
                float rg = mx - mn;
                s_mv = 0.5f * (mn + mx);
                s_sv = rg * (1.0f / 254.0f);
                s_isv = (rg > 1e-30f) ? (254.0f / rg) : 0.0f;
                s_sum = sm;
            }
        }
        __syncthreads();
        const float mv = s_mv, sv = s_sv, isv = s_isv, sumv = s_sum;

        // 2) quantize x directly from global (one float4 per thread)
        {
            float4 xv = __ldcg((const float4*)x + tid);
            int t0 = max(-127, min(127, __float2int_rn((xv.x - mv) * isv)));
            int t1 = max(-127, min(127, __float2int_rn((xv.y - mv) * isv)));
            int t2 = max(-127, min(127, __float2int_rn((xv.z - mv) * isv)));
            int t3 = max(-127, min(127, __float2int_rn((xv.w - mv) * isv)));
            ((char4*)tsm)[tid] = make_char4((char)t0, (char)t1, (char)t2, (char)t3);
        }
        __syncthreads();

        // 3) dot on the prefetched row registers (dp4a int8 x int8, exact)
        {
            int d = 0;
            int4 t0 = ((const int4*)tsm)[0 * 32 + lane];
            int4 t1 = ((const int4*)tsm)[1 * 32 + lane];
            int4 t2 = ((const int4*)tsm)[2 * 32 + lane];
            int4 t3 = ((const int4*)tsm)[3 * 32 + lane];
            d = __dp4a((int)ph0.x, t0.x, d); d = __dp4a((int)ph0.y, t0.y, d);
            d = __dp4a((int)ph0.z, t0.z, d); d = __dp4a((int)ph0.w, t0.w, d);
            d = __dp4a((int)ph1.x, t1.x, d); d = __dp4a((int)ph1.y, t1.y, d);
            d = __dp4a((int)ph1.z, t1.z, d); d = __dp4a((int)ph1.w, t1.w, d);
            d = __dp4a((int)ph2.x, t2.x, d); d = __dp4a((int)ph2.y, t2.y, d);
            d = __dp4a((int)ph2.z, t2.z, d); d = __dp4a((int)ph2.w, t2.w, d);
            d = __dp4a((int)ph3.x, t3.x, d); d = __dp4a((int)ph3.y, t3.y, d);
            d = __dp4a((int)ph3.z, t3.z, d); d = __dp4a((int)ph3.w, t3.w, d);
            int4 t4 = ((const int4*)tsm)[4 * 32 + lane];
            int4 t5 = ((const int4*)tsm)[5 * 32 + lane];
            int4 t6 = ((const int4*)tsm)[6 * 32 + lane];
            int4 t7 = ((const int4*)tsm)[7 * 32 + lane];
            d = __dp4a((int)ph4.x, t4.x, d); d = __dp4a((int)ph4.y, t4.y, d);
            d = __dp4a((int)ph4.z, t4.z, d); d = __dp4a((int)ph4.w, t4.w, d);
            d = __dp4a((int)ph5.x, t5.x, d); d = __dp4a((int)ph5.y, t5.y, d);
            d = __dp4a((int)ph5.z, t5.z, d); d = __dp4a((int)ph5.w, t5.w, d);
            d = __dp4a((int)ph6.x, t6.x, d); d = __dp4a((int)ph6.y, t6.y, d);
            d = __dp4a((int)ph6.z, t6.z, d); d = __dp4a((int)ph6.w, t6.w, d);
            d = __dp4a((int)ph7.x, t7.x, d); d = __dp4a((int)ph7.y, t7.y, d);
            d = __dp4a((int)ph7.z, t7.z, d); d = __dp4a((int)ph7.w, t7.w, d);
            d = wsumi(d);
            if (lane == 0) {
                float kv = (mv * (float)rs[gw] + sv * (float)d + 64.0f * sumv) * (1.0f / 255.0f);
                float yv = MUV / (kv + EPSV);
                y[gw] = yv;
                yvs[wid] = yv;
            }
        }
        __syncthreads();

        // 4) publish this block's y-stats
        if (tid < 32) {
            float v = yvs[lane];
            float mn = v, mx = v, sm = v;
#pragma unroll
            for (int o = 16; o > 0; o >>= 1) {
                mn = fminf(mn, __shfl_down_sync(0xffffffffu, mn, o));
                mx = fmaxf(mx, __shfl_down_sync(0xffffffffu, mx, o));
                sm += __shfl_down_sync(0xffffffffu, sm, o);
            }
            if (tid == 0) g_bstat[blockIdx.x] = make_float4(mn, mx, sm, 0.f);
        }

        // 5) prefetch first half of NEXT pass's row (loss uses g_S)
        {
            const char* Mn = (half == 2 * NITER - 1) ? g_S : (dir ? g_ST : g_S);
            prow = (const uint4*)(Mn + (size_t)gw * NP) + lane;
            ph0 = prow[0 * 32];
            ph1 = prow[1 * 32];
            ph2 = prow[2 * 32];
            ph3 = prow[3 * 32];
        }
        bar++; gsync(bar);
    }

    // ---- loss: sum_ij u_i * (S_ij+64)/255 * C_ij * v_j ----
    // ph0..ph3 hold the first half of this warp's S row already.
    ((float4*)ysm)[tid] = __ldcg((const float4*)g_v + tid);
    __syncthreads();

    float part;
    {
        const int r = gw;
        const uint4* pc = (const uint4*)((const char*)g_C + (size_t)r * NP * 2) + lane * 2;
        float s = 0.f;
        uint4 phs[8];
        phs[0] = ph0; phs[1] = ph1; phs[2] = ph2; phs[3] = ph3;
        phs[4] = prow[4 * 32]; phs[5] = prow[5 * 32];
        phs[6] = prow[6 * 32]; phs[7] = prow[7 * 32];
#pragma unroll
        for (int k = 0; k < 8; k++) {
            uint4 qs  = phs[k];
            uint4 qc0 = pc[k * 64];
            uint4 qc1 = pc[k * 64 + 1];
            const __half2* h0 = (const __half2*)&qc0;
            const __half2* h1 = (const __half2*)&qc1;
            int e = (lane + k * 32) * 16;
#pragma unroll
            for (int w = 0; w < 4; w++) {
                int word = ((const int*)&qs)[w];
                const __half2* hh = (w < 2) ? (h0 + 2 * w) : (h1 + 2 * (w - 2));
                float2 c0 = __half22float2(hh[0]);
                float2 c1 = __half22float2(hh[1]);
                int s0 = (word << 24) >> 24;
                int s1 = (word << 16) >> 24;
                int s2 = (word << 8)  >> 24;
                int s3 =  word        >> 24;
                int eb = e + 4 * w;
                s += (float)(s0 + 64) * c0.x * ysm[eb + 0];
                s += (float)(s1 + 64) * c0.y * ysm[eb + 1];
                s += (float)(s2 + 64) * c1.x * ysm[eb + 2];
                s += (float)(s3 + 64) * c1.y * ysm[eb + 3];
            }
        }
        s = wsumf(s);
        part = s * (1.0f / 255.0f);
    }
    if (lane == 0) rsm[wid] = part * __ldcg(&g_u[gw]);
    __syncthreads();
    if (tid == 0) {
        float b = 0.f;
#pragma unroll
        for (int q = 0; q < 32; q++) b += rsm[q];
        g_part[blockIdx.x] = b;
    }
    bar++; gsync(bar);
    if (blockIdx.x == 0 && tid == 0) {
        float t = 0.f;
        for (int i = 0; i < NBLK; i++) t += __ldcg((const float*)&g_part[i]);
        g_result += t;
    }
}

// ---------------- finalize + reset barrier state ---------------------------
__global__ void fin_k(float* out) {
    if (threadIdx.x == 0) out[0] = g_result * (1.0f / 3.0f);
    if (threadIdx.x < NBLK) g_flag[threadIdx.x * 32] = 0;
}

// ---------------- launch ---------------------------------------------------
extern "C" void kernel_launch(void* const* d_in, const int* in_sizes, int n_in,
                              void* d_out, int out_size) {
    const float* z0 = (const float*)d_in[0];
    const float* z1 = (const float*)d_in[1];
    const float* z2 = (const float*)d_in[2];
    float* out = (float*)d_out;

    norms_k<<<1536, 256>>>(z0, z1, z2);

    const float* Xs[3] = { z0, z0, z1 };
    const float* Ys[3] = { z1, z2, z2 };
    const int    xi[3] = { 0, 0, 1 };
    const int    yi[3] = { 1, 2, 2 };

    for (int p = 0; p < 3; p++) {
        gemm_expK_k<<<1024, 256>>>(Xs[p], Ys[p], xi[p], yi[p]);
        sink_k<<<NBLK, NTHR>>>(p);
    }
    fin_k<<<1, 256>>>(out);
}

// round 9
// speedup vs baseline: 2.2810x; 1.4562x over previous
#include <cuda_runtime.h>
#include <cuda_fp16.h>
#include <cstdint>

#define NP 4096
#define DI 128
#define REGINV 20.0f          // 1/0.05
#define MUV (1.0f/4096.0f)
#define EPSV 1e-8f
#define NITER 100
#define NBLK 128
#define NTHR 1024
#define NWARP (NBLK*(NTHR/32))   // 4096 == NP

// ---------------- device scratch (no allocations allowed) ----------------
__device__ char   g_S [3][(size_t)NP * NP];   // 48 MB  S[i][j] = round(255*K)-64
__device__ char   g_ST[3][(size_t)NP * NP];   // 48 MB  transpose
__device__ __half g_C [3][(size_t)NP * NP];   // 96 MB  clipped cost (streamed)
__device__ int    g_rsS[3][NP];
__device__ int    g_rsT[3][NP];
__device__ float  g_u[3][NP];
__device__ float  g_v[3][NP];
__device__ float  g_norm[3][NP];
__device__ float  g_part[NBLK];
__device__ float4 g_bstat[3][NBLK];           // per-pair, per-block (mn,mx,sum) of 32 y's
__device__ float  g_result;
__device__ int    g_flag[NBLK * 32];          // one 128B line per block

__device__ __forceinline__ float wsumf(float v) {
#pragma unroll
    for (int o = 16; o > 0; o >>= 1) v += __shfl_down_sync(0xffffffffu, v, o);
    return v;
}
__device__ __forceinline__ int wsumi(int v) {
#pragma unroll
    for (int o = 16; o > 0; o >>= 1) v += __shfl_down_sync(0xffffffffu, v, o);
    return v;
}

// ---------------- one-hop grid barrier, release/acquire -------------------
__device__ __forceinline__ void gsync(int bar) {
    __syncthreads();
    if (threadIdx.x == 0) {
        __threadfence();
        asm volatile("st.release.gpu.global.b32 [%0], %1;"
                     :: "l"(&g_flag[blockIdx.x * 32]), "r"(bar) : "memory");
    }
    if (threadIdx.x < NBLK) {
        int v;
        do {
            asm volatile("ld.acquire.gpu.global.b32 %0, [%1];"
                         : "=r"(v) : "l"(&g_flag[threadIdx.x * 32]) : "memory");
        } while (v < bar);
    }
    __syncthreads();
}

// ---------------- row squared norms (+ zero g_result) ---------------------
__global__ void norms_k(const float* __restrict__ z0, const float* __restrict__ z1,
                        const float* __restrict__ z2) {
    if (blockIdx.x == 0 && threadIdx.x == 0) g_result = 0.f;
    int w    = (blockIdx.x * blockDim.x + threadIdx.x) >> 5;
    int lane = threadIdx.x & 31;
    if (w >= 3 * NP) return;
    const float* z = (w < NP) ? z0 : (w < 2 * NP ? z1 : z2);
    int r = w & (NP - 1);
    float4 f = *(const float4*)(z + (size_t)r * DI + lane * 4);
    float s = f.x * f.x + f.y * f.y + f.z * f.z + f.w * f.w;
    s = wsumf(s);
    if (lane == 0) ((float*)g_norm)[w] = s;
}

// ---------------- GEMM (128x128 tile, 8x8/thread) -> S, ST, C -------------
struct GSmem {
    union {
        struct { float xs[16][132]; float ys[16][132]; } l;
        char tr[128][144];
    };
};

__global__ void __launch_bounds__(256, 2) gemm_expK_k(
        const float* __restrict__ X, const float* __restrict__ Y,
        int nxi, int nyi, int pr) {
    __shared__ __align__(16) GSmem sm;

    const float* nx = g_norm[nxi];
    const float* ny = g_norm[nyi];
    char*   So = g_S[pr];
    char*   To = g_ST[pr];
    __half* Co = g_C[pr];

    int tid = threadIdx.x;
    int tx = tid & 15, ty = tid >> 4;
    int i0 = (blockIdx.x >> 5) << 7;
    int j0 = (blockIdx.x & 31) << 7;

    float acc[8][8];
#pragma unroll
    for (int a = 0; a < 8; a++)
#pragma unroll
        for (int b = 0; b < 8; b++) acc[a][b] = 0.f;

    for (int kk = 0; kk < DI; kk += 16) {
        __syncthreads();
#pragma unroll
        for (int q = 0; q < 2; q++) {
            int f = tid + q * 256;
            int r = f >> 2;
            int kq = (f & 3) * 4;
            float4 xv = *(const float4*)(X + (size_t)(i0 + r) * DI + kk + kq);
            float4 yv = *(const float4*)(Y + (size_t)(j0 + r) * DI + kk + kq);
            sm.l.xs[kq + 0][r] = xv.x; sm.l.xs[kq + 1][r] = xv.y;
            sm.l.xs[kq + 2][r] = xv.z; sm.l.xs[kq + 3][r] = xv.w;
            sm.l.ys[kq + 0][r] = yv.x; sm.l.ys[kq + 1][r] = yv.y;
            sm.l.ys[kq + 2][r] = yv.z; sm.l.ys[kq + 3][r] = yv.w;
        }
        __syncthreads();
#pragma unroll 4
        for (int k = 0; k < 16; k++) {
            float4 xa = *(const float4*)&sm.l.xs[k][ty * 4];
            float4 xb = *(const float4*)&sm.l.xs[k][64 + ty * 4];
            float4 ya = *(const float4*)&sm.l.ys[k][tx * 4];
            float4 yb = *(const float4*)&sm.l.ys[k][64 + tx * 4];
            float xr[8] = { xa.x, xa.y, xa.z, xa.w, xb.x, xb.y, xb.z, xb.w };
            float yr[8] = { ya.x, ya.y, ya.z, ya.w, yb.x, yb.y, yb.z, yb.w };
#pragma unroll
            for (int a = 0; a < 8; a++)
#pragma unroll
                for (int b = 0; b < 8; b++) acc[a][b] += xr[a] * yr[b];
        }
    }
    __syncthreads();   // xs/ys dead; tr may now be written

#pragma unroll
    for (int a = 0; a < 8; a++) {
        int il = (a < 4) ? (ty * 4 + a) : (64 + ty * 4 + a - 4);
        int i = i0 + il;
        float ni = __ldg(nx + i);
#pragma unroll
        for (int p = 0; p < 2; p++) {
            int jl0 = p * 64 + tx * 4;
            unsigned sq = 0;
            alignas(8) __half hc[4];
#pragma unroll
            for (int e = 0; e < 4; e++) {
                int j = j0 + jl0 + e;
                float c  = fmaxf(ni + __ldg(ny + j) - 2.0f * acc[a][p * 4 + e], 0.0f);
                float kf = __expf(-REGINV * c);
                int q = __float2int_rn(kf * 255.f) - 64;
                q = min(q, 127);
                hc[e] = __float2half(c);
                char qc = (char)q;
                sq |= ((unsigned)(unsigned char)qc) << (8 * e);
                sm.tr[jl0 + e][il] = qc;
            }
            *(unsigned*)&So[(size_t)i * NP + j0 + jl0] = sq;
            __stcs((unsigned long long*)&Co[(size_t)i * NP + j0 + jl0],
                   *(const unsigned long long*)hc);      // streamed: read-once data
        }
    }
    __syncthreads();
    {
        int jj = tid >> 1;
        int ii = (tid & 1) * 64;
#pragma unroll
        for (int q = 0; q < 4; q++)
            *(uint4*)&To[(size_t)(j0 + jj) * NP + i0 + ii + q * 16] =
                *(const uint4*)&sm.tr[jj][ii + q * 16];
    }
}

// ---------------- persistent Sinkhorn + loss, ALL 3 pairs ------------------
__global__ void __launch_bounds__(NTHR, 1) sink_k() {
    __shared__ __align__(16) float ysm[NP];       // 16 KB (loss staging)
    __shared__ __align__(16) char  tsm[3][NP];    // 12 KB quantized x per pair
    __shared__ float yvs[3][32];
    __shared__ float rsm[32];
    __shared__ float s_mv[3], s_sv[3], s_isv[3], s_sum[3];

    const int tid  = threadIdx.x;
    const int lane = tid & 31;
    const int wid  = tid >> 5;
    const int gw   = blockIdx.x * (NTHR / 32) + wid;   // 0..4095 == row
    int bar = 0;

    // ---- pre-pass: row sums of S/ST for 3 pairs, u := 1, bstat init ----
#pragma unroll 1
    for (int h = 0; h < 6; h++) {
        int p = h >> 1;
        const char* row = ((h & 1) ? g_ST[p] : g_S[p]) + (size_t)gw * NP;
        const uint4* pp = (const uint4*)row + lane;
        int d = 0;
#pragma unroll
        for (int k = 0; k < 8; k++) {
            uint4 q = pp[k * 32];
            d = __dp4a((int)q.x, 0x01010101, d);
            d = __dp4a((int)q.y, 0x01010101, d);
            d = __dp4a((int)q.z, 0x01010101, d);
            d = __dp4a((int)q.w, 0x01010101, d);
        }
        d = wsumi(d);
        if (lane == 0) ((h & 1) ? g_rsT[p] : g_rsS[p])[gw] = d;
    }
    {
        int gi = blockIdx.x * NTHR + tid;
        if (gi < 3 * NP) ((float*)g_u)[gi] = 1.0f;
    }
    if (tid < 3) g_bstat[tid][blockIdx.x] = make_float4(1.0f, 1.0f, 32.0f, 0.0f);
    bar++; gsync(bar);

    // ---- 200 half-iterations, 3 pairs each ----
    for (int half = 0; half < 2 * NITER; half++) {
        const int dir = half & 1;     // 0: v = f(K^T u)  (x=u, M=ST);  1: u = f(K v)

        // 1) per-pair global stats, one warp per pair
        if (wid < 3) {
            float mn = 1e30f, mx = -1e30f, sm = 0.f;
#pragma unroll
            for (int q = 0; q < 4; q++) {
                float4 b = __ldcg(&g_bstat[wid][lane + q * 32]);
                mn = fminf(mn, b.x); mx = fmaxf(mx, b.y); sm += b.z;
            }
#pragma unroll
            for (int o = 16; o > 0; o >>= 1) {
                mn = fminf(mn, __shfl_down_sync(0xffffffffu, mn, o));
                mx = fmaxf(mx, __shfl_down_sync(0xffffffffu, mx, o));
                sm += __shfl_down_sync(0xffffffffu, sm, o);
            }
            if (lane == 0) {
                float rg = mx - mn;
                s_mv[wid] = 0.5f * (mn + mx);
                s_sv[wid] = rg * (1.0f / 254.0f);
                s_isv[wid] = (rg > 1e-30f) ? (254.0f / rg) : 0.0f;
                s_sum[wid] = sm;
            }
        }
        __syncthreads();

        // 2) quantize the 3 x-vectors (one float4 per thread per pair)
#pragma unroll
        for (int p = 0; p < 3; p++) {
            const float* x = dir ? g_v[p] : g_u[p];
            float4 xv = __ldcg((const float4*)x + tid);
            float mv = s_mv[p], isv = s_isv[p];
            int t0 = max(-127, min(127, __float2int_rn((xv.x - mv) * isv)));
            int t1 = max(-127, min(127, __float2int_rn((xv.y - mv) * isv)));
            int t2 = max(-127, min(127, __float2int_rn((xv.z - mv) * isv)));
            int t3 = max(-127, min(127, __float2int_rn((xv.w - mv) * isv)));
            ((char4*)tsm[p])[tid] = make_char4((char)t0, (char)t1, (char)t2, (char)t3);
        }
        __syncthreads();

        // 3) per-pair row dot (dp4a int8 x int8, exact); sequential pairs
#pragma unroll 1
        for (int p = 0; p < 3; p++) {
            const char* M = dir ? g_S[p] : g_ST[p];
            const uint4* pr = (const uint4*)(M + (size_t)gw * NP) + lane;
            int d = 0;
#pragma unroll
            for (int t = 0; t < 8; t += 4) {
                uint4 a0 = pr[(t + 0) * 32];
                uint4 a1 = pr[(t + 1) * 32];
                uint4 a2 = pr[(t + 2) * 32];
                uint4 a3 = pr[(t + 3) * 32];
                int4 t0 = ((const int4*)tsm[p])[(t + 0) * 32 + lane];
                int4 t1 = ((const int4*)tsm[p])[(t + 1) * 32 + lane];
                int4 t2 = ((const int4*)tsm[p])[(t + 2) * 32 + lane];
                int4 t3 = ((const int4*)tsm[p])[(t + 3) * 32 + lane];
                d = __dp4a((int)a0.x, t0.x, d); d = __dp4a((int)a0.y, t0.y, d);
                d = __dp4a((int)a0.z, t0.z, d); d = __dp4a((int)a0.w, t0.w, d);
                d = __dp4a((int)a1.x, t1.x, d); d = __dp4a((int)a1.y, t1.y, d);
                d = __dp4a((int)a1.z, t1.z, d); d = __dp4a((int)a1.w, t1.w, d);
                d = __dp4a((int)a2.x, t2.x, d); d = __dp4a((int)a2.y, t2.y, d);
                d = __dp4a((int)a2.z, t2.z, d); d = __dp4a((int)a2.w, t2.w, d);
                d = __dp4a((int)a3.x, t3.x, d); d = __dp4a((int)a3.y, t3.y, d);
                d = __dp4a((int)a3.z, t3.z, d); d = __dp4a((int)a3.w, t3.w, d);
            }
            d = wsumi(d);
            if (lane == 0) {
                const int* rs = dir ? g_rsS[p] : g_rsT[p];
                float kv = (s_mv[p] * (float)rs[gw] + s_sv[p] * (float)d
                            + 64.0f * s_sum[p]) * (1.0f / 255.0f);
                float yv = MUV / (kv + EPSV);
                (dir ? g_u[p] : g_v[p])[gw] = yv;
                yvs[p][wid] = yv;
            }
        }
        __syncthreads();

        // 4) publish per-pair block stats
        if (wid < 3) {
            float v = yvs[wid][lane];
            float mn = v, mx = v, sm = v;
#pragma unroll
            for (int o = 16; o > 0; o >>= 1) {
                mn = fminf(mn, __shfl_down_sync(0xffffffffu, mn, o));
                mx = fmaxf(mx, __shfl_down_sync(0xffffffffu, mx, o));
                sm += __shfl_down_sync(0xffffffffu, sm, o);
            }
            if (lane == 0) g_bstat[wid][blockIdx.x] = make_float4(mn, mx, sm, 0.f);
        }
        bar++; gsync(bar);
    }

    // ---- loss: sum over pairs of sum_ij u_i (S_ij+64)/255 C_ij v_j ----
    float part = 0.f;
#pragma unroll 1
    for (int p = 0; p < 3; p++) {
        __syncthreads();
        ((float4*)ysm)[tid] = __ldcg((const float4*)g_v[p] + tid);
        __syncthreads();
        const uint4* ps = (const uint4*)(g_S[p] + (size_t)gw * NP) + lane;
        const int4*  pc = (const int4*)((const char*)g_C[p] + (size_t)gw * NP * 2) + lane * 2;
        float s = 0.f;
#pragma unroll
        for (int k = 0; k < 8; k++) {
            uint4 qs = ps[k * 32];
            int4 qc0 = __ldcs(&pc[k * 64]);
            int4 qc1 = __ldcs(&pc[k * 64 + 1]);
            const __half2* h0 = (const __half2*)&qc0;
            const __half2* h1 = (const __half2*)&qc1;
            int e = (lane + k * 32) * 16;
#pragma unroll
            for (int w = 0; w < 4; w++) {
                int word = ((const int*)&qs)[w];
                const __half2* hh = (w < 2) ? (h0 + 2 * w) : (h1 + 2 * (w - 2));
                float2 c0 = __half22float2(hh[0]);
                float2 c1 = __half22float2(hh[1]);
                int s0 = (word << 24) >> 24;
                int s1 = (word << 16) >> 24;
                int s2 = (word << 8)  >> 24;
                int s3 =  word        >> 24;
                int eb = e + 4 * w;
                s += (float)(s0 + 64) * c0.x * ysm[eb + 0];
                s += (float)(s1 + 64) * c0.y * ysm[eb + 1];
                s += (float)(s2 + 64) * c1.x * ysm[eb + 2];
                s += (float)(s3 + 64) * c1.y * ysm[eb + 3];
            }
        }
        s = wsumf(s);
        if (lane == 0) part += s * (1.0f / 255.0f) * __ldcg(&g_u[p][gw]);
    }
    if (lane == 0) rsm[wid] = part;
    __syncthreads();
    if (tid == 0) {
        float b = 0.f;
#pragma unroll
        for (int q = 0; q < 32; q++) b += rsm[q];
        g_part[blockIdx.x] = b;
    }
    bar++; gsync(bar);
    if (blockIdx.x == 0 && tid == 0) {
        float t = 0.f;
        for (int i = 0; i < NBLK; i++) t += __ldcg((const float*)&g_part[i]);
        g_result = t;
    }
}

// ---------------- finalize + reset barrier state ---------------------------
__global__ void fin_k(float* out) {
    if (threadIdx.x == 0) out[0] = g_result * (1.0f / 3.0f);
    if (threadIdx.x < NBLK) g_flag[threadIdx.x * 32] = 0;
}

// ---------------- launch ---------------------------------------------------
extern "C" void kernel_launch(void* const* d_in, const int* in_sizes, int n_in,
                              void* d_out, int out_size) {
    const float* z0 = (const float*)d_in[0];
    const float* z1 = (const float*)d_in[1];
    const float* z2 = (const float*)d_in[2];
    float* out = (float*)d_out;

    norms_k<<<1536, 256>>>(z0, z1, z2);

    const float* Xs[3] = { z0, z0, z1 };
    const float* Ys[3] = { z1, z2, z2 };
    const int    xi[3] = { 0, 0, 1 };
    const int    yi[3] = { 1, 2, 2 };

    for (int p = 0; p < 3; p++)
        gemm_expK_k<<<1024, 256>>>(Xs[p], Ys[p], xi[p], yi[p], p);
    sink_k<<<NBLK, NTHR>>>();
    fin_k<<<1, 256>>>(out);
}

// round 11
// speedup vs baseline: 2.4518x; 1.0749x over previous
#include <cuda_runtime.h>
#include <cuda_fp16.h>
#include <cstdint>

#define NP 4096
#define DI 128
#define REGINV 20.0f          // 1/0.05
#define MUV (1.0f/4096.0f)
#define EPSV 1e-8f
#define NITER 100
#define NBLK 128
#define NTHR 1024
#define NWARP (NBLK*(NTHR/32))   // 4096 == NP

#define GP 136                 // As/Bs pitch in halves (68 words == 4 mod 32 -> conflict-free)
#define SP 144                 // S staging pitch in bytes (16B aligned rows)
#define CP 136                 // C staging pitch in halves
#define GSM_BYTES (2*128*SP + 128*CP*2)   // 36864 + 34816 = 71680 >= 2*128*GP*2 = 69632

// ---------------- device scratch (no allocations allowed) ----------------
__device__ char   g_S [3][(size_t)NP * NP];   // 48 MB
__device__ char   g_ST[3][(size_t)NP * NP];   // 48 MB
__device__ __half g_C [3][(size_t)NP * NP];   // 96 MB (streamed)
__device__ __half g_zh[3][(size_t)NP * DI];   // fp16 inputs (3 MB)
__device__ int    g_rsS[3][NP];
__device__ int    g_rsT[3][NP];
__device__ float  g_u[3][NP];
__device__ float  g_v[3][NP];
__device__ float  g_norm[3][NP];
__device__ float  g_part[NBLK];
__device__ float4 g_bstat[3][NBLK];
__device__ float  g_result;
__device__ int    g_flag[NBLK * 32];

__device__ __forceinline__ float wsumf(float v) {
#pragma unroll
    for (int o = 16; o > 0; o >>= 1) v += __shfl_down_sync(0xffffffffu, v, o);
    return v;
}
__device__ __forceinline__ int wsumi(int v) {
#pragma unroll
    for (int o = 16; o > 0; o >>= 1) v += __shfl_down_sync(0xffffffffu, v, o);
    return v;
}

// ---------------- one-hop grid barrier, release/acquire -------------------
__device__ __forceinline__ void gsync(int bar) {
    __syncthreads();
    if (threadIdx.x == 0) {
        __threadfence();
        asm volatile("st.release.gpu.global.b32 [%0], %1;"
                     :: "l"(&g_flag[blockIdx.x * 32]), "r"(bar) : "memory");
    }
    if (threadIdx.x < NBLK) {
        int v;
        do {
            asm volatile("ld.acquire.gpu.global.b32 %0, [%1];"
                         : "=r"(v) : "l"(&g_flag[threadIdx.x * 32]) : "memory");
        } while (v < bar);
    }
    __syncthreads();
}

// ------- row sq-norms + fp16 convert + zero rs/result ---------------------
__global__ void norms_k(const float* __restrict__ z0, const float* __restrict__ z1,
                        const float* __restrict__ z2) {
    int gt = blockIdx.x * blockDim.x + threadIdx.x;
    if (gt == 0) g_result = 0.f;
    if (gt < 3 * NP) { ((int*)g_rsS)[gt] = 0; ((int*)g_rsT)[gt] = 0; }
    int w    = gt >> 5;
    int lane = threadIdx.x & 31;
    if (w >= 3 * NP) return;
    int iz = (w < NP) ? 0 : (w < 2 * NP ? 1 : 2);
    const float* z = (iz == 0) ? z0 : (iz == 1 ? z1 : z2);
    int r = w & (NP - 1);
    float4 f = *(const float4*)(z + (size_t)r * DI + lane * 4);
    // fp16 copy
    __half2 h01 = __floats2half2_rn(f.x, f.y);
    __half2 h23 = __floats2half2_rn(f.z, f.w);
    uint2 pk = { *(unsigned*)&h01, *(unsigned*)&h23 };
    *(uint2*)(g_zh[iz] + (size_t)r * DI + lane * 4) = pk;
    float s = f.x * f.x + f.y * f.y + f.z * f.z + f.w * f.w;
    s = wsumf(s);
    if (lane == 0) ((float*)g_norm)[w] = s;
}

// -------- HMMA GEMM (128x128 tile, 8 warps) -> S, ST, C, rowsums ----------
__device__ __forceinline__ void mma16816(float* d, const unsigned* a,
                                         unsigned b0, unsigned b1) {
    asm volatile(
        "mma.sync.aligned.m16n8k16.row.col.f32.f16.f16.f32 "
        "{%0,%1,%2,%3}, {%4,%5,%6,%7}, {%8,%9}, {%0,%1,%2,%3};"
        : "+f"(d[0]), "+f"(d[1]), "+f"(d[2]), "+f"(d[3])
        : "r"(a[0]), "r"(a[1]), "r"(a[2]), "r"(a[3]), "r"(b0), "r"(b1));
}

__global__ void __launch_bounds__(256, 2) gemm_expK_k(int xi, int yi, int pr) {
    extern __shared__ __align__(16) char smraw[];
    __half* As = (__half*)smraw;
    __half* Bs = As + 128 * GP;

    const float* nx = g_norm[xi];
    const float* ny = g_norm[yi];
    const __half* Xh = g_zh[xi];
    const __half* Yh = g_zh[yi];

    const int tid = threadIdx.x;
    const int i0 = (blockIdx.x >> 5) << 7;
    const int j0 = (blockIdx.x & 31) << 7;

    // stage A,B tiles (fp16, 128x128 each)
    {
        int r = tid >> 1, seg = (tid & 1) * 64;
#pragma unroll
        for (int q = 0; q < 8; q++) {
            *(uint4*)&As[r * GP + seg + q * 8] =
                *(const uint4*)(Xh + (size_t)(i0 + r) * DI + seg + q * 8);
            *(uint4*)&Bs[r * GP + seg + q * 8] =
                *(const uint4*)(Yh + (size_t)(j0 + r) * DI + seg + q * 8);
        }
    }
    __syncthreads();

    const int lane = tid & 31;
    const int warp = tid >> 5;
    const int gr = lane >> 2, ct = lane & 3;
    const int rb = (warp & 3) * 32;
    const int nb = (warp >> 2) * 64;

    float acc[2][8][4];
#pragma unroll
    for (int mt = 0; mt < 2; mt++)
#pragma unroll
        for (int nt = 0; nt < 8; nt++)
#pragma unroll
            for (int e = 0; e < 4; e++) acc[mt][nt][e] = 0.f;

#pragma unroll
    for (int ks = 0; ks < 8; ks++) {
        const int kb = ks * 16;
        unsigned a[2][4];
#pragma unroll
        for (int mt = 0; mt < 2; mt++) {
            int r0 = rb + mt * 16 + gr;
            a[mt][0] = *(const unsigned*)&As[r0 * GP + kb + 2 * ct];
            a[mt][1] = *(const unsigned*)&As[(r0 + 8) * GP + kb + 2 * ct];
            a[mt][2] = *(const unsigned*)&As[r0 * GP + kb + 8 + 2 * ct];
            a[mt][3] = *(const unsigned*)&As[(r0 + 8) * GP + kb + 8 + 2 * ct];
        }
#pragma unroll
        for (int nt = 0; nt < 8; nt++) {
            int n0 = nb + nt * 8 + gr;
            unsigned b0 = *(const unsigned*)&Bs[n0 * GP + kb + 2 * ct];
            unsigned b1 = *(const unsigned*)&Bs[n0 * GP + kb + 8 + 2 * ct];
            mma16816(acc[0][nt], a[0], b0, b1);
            mma16816(acc[1][nt], a[1], b0, b1);
        }
    }
    __syncthreads();   // As/Bs dead; reuse smem for staging

    char*   Sr = smraw;                         // [128][SP] row-layout S bytes
    char*   Sc = smraw + 128 * SP;              // [128][SP] col-layout S bytes
    __half* Cm = (__half*)(smraw + 2 * 128 * SP); // [128][CP] C halves

    // epilogue: exact same math as before (exp/quantize), from fragments
#pragma unroll
    for (int mt = 0; mt < 2; mt++) {
        int ila = rb + mt * 16 + gr;
        int ilb = ila + 8;
        float nxa = __ldg(nx + i0 + ila);
        float nxb = __ldg(nx + i0 + ilb);
#pragma unroll
        for (int nt = 0; nt < 8; nt++) {
            int jl = nb + nt * 8 + 2 * ct;
            float ny0 = __ldg(ny + j0 + jl);
            float ny1 = __ldg(ny + j0 + jl + 1);
            float ca0 = fmaxf(nxa + ny0 - 2.0f * acc[mt][nt][0], 0.0f);
            float ca1 = fmaxf(nxa + ny1 - 2.0f * acc[mt][nt][1], 0.0f);
            float cb0 = fmaxf(nxb + ny0 - 2.0f * acc[mt][nt][2], 0.0f);
            float cb1 = fmaxf(nxb + ny1 - 2.0f * acc[mt][nt][3], 0.0f);
            int qa0 = min(127, __float2int_rn(__expf(-REGINV * ca0) * 255.f) - 64);
            int qa1 = min(127, __float2int_rn(__expf(-REGINV * ca1) * 255.f) - 64);
            int qb0 = min(127, __float2int_rn(__expf(-REGINV * cb0) * 255.f) - 64);
            int qb1 = min(127, __float2int_rn(__expf(-REGINV * cb1) * 255.f) - 64);
            *(short*)&Sr[ila * SP + jl] = (short)((qa0 & 0xFF) | (qa1 << 8));
            *(short*)&Sr[ilb * SP + jl] = (short)((qb0 & 0xFF) | (qb1 << 8));
            Sc[jl * SP + ila] = (char)qa0;       Sc[jl * SP + ilb] = (char)qb0;
            Sc[(jl + 1) * SP + ila] = (char)qa1; Sc[(jl + 1) * SP + ilb] = (char)qb1;
            __half2 ha = __floats2half2_rn(ca0, ca1);
            __half2 hb = __floats2half2_rn(cb0, cb1);
            *(unsigned*)&Cm[ila * CP + jl] = *(unsigned*)&ha;
            *(unsigned*)&Cm[ilb * CP + jl] = *(unsigned*)&hb;
        }
    }
    __syncthreads();

    // writeout: S rows + rowsum atomics; ST rows (= S cols) + rowsum atomics; C
    {
        int r = tid >> 1, ii = (tid & 1) * 64;
        int rs = 0;
#pragma unroll
        for (int q = 0; q < 4; q++) {
            uint4 w = *(const uint4*)&Sr[r * SP + ii + q * 16];
            *(uint4*)&g_S[pr][(size_t)(i0 + r) * NP + j0 + ii + q * 16] = w;
            rs = __dp4a((int)w.x, 0x01010101, rs); rs = __dp4a((int)w.y, 0x01010101, rs);
            rs = __dp4a((int)w.z, 0x01010101, rs); rs = __dp4a((int)w.w, 0x01010101, rs);
        }
        atomicAdd(&g_rsS[pr][i0 + r], rs);
        int ts = 0;
#pragma unroll
        for (int q = 0; q < 4; q++) {
            uint4 w = *(const uint4*)&Sc[r * SP + ii + q * 16];
            *(uint4*)&g_ST[pr][(size_t)(j0 + r) * NP + i0 + ii + q * 16] = w;
            ts = __dp4a((int)w.x, 0x01010101, ts); ts = __dp4a((int)w.y, 0x01010101, ts);
            ts = __dp4a((int)w.z, 0x01010101, ts); ts = __dp4a((int)w.w, 0x01010101, ts);
        }
        atomicAdd(&g_rsT[pr][j0 + r], ts);
#pragma unroll
        for (int q = 0; q < 8; q++)
            __stcs((uint4*)&g_C[pr][(size_t)(i0 + r) * NP + j0 + ii + q * 8],
                   *(const uint4*)&Cm[r * CP + ii + q * 8]);
    }
}

// ---------------- persistent Sinkhorn + loss, ALL 3 pairs ------------------
__global__ void __launch_bounds__(NTHR, 1) sink_k() {
    __shared__ __align__(16) float ysm[NP];
    __shared__ __align__(16) char  tsm[3][NP];
    __shared__ float yvs[3][32];
    __shared__ float rsm[32];
    __shared__ float s_mv[3], s_sv[3], s_isv[3], s_sum[3];

    const int tid  = threadIdx.x;
    const int lane = tid & 31;
    const int wid  = tid >> 5;
    const int gw   = blockIdx.x * (NTHR / 32) + wid;   // 0..4095 == row
    int bar = 0;

    // ---- init: u := 1, bstat init (row sums were computed by GEMM atomics) ----
    {
        int gi = blockIdx.x * NTHR + tid;
        if (gi < 3 * NP) ((float*)g_u)[gi] = 1.0f;
    }
    if (tid < 3) g_bstat[tid][blockIdx.x] = make_float4(1.0f, 1.0f, 32.0f, 0.0f);
    bar++; gsync(bar);

    // ---- 200 half-iterations, 3 pairs each ----
    for (int half = 0; half < 2 * NITER; half++) {
        const int dir = half & 1;     // 0: v = f(K^T u);  1: u = f(K v)

        // 1) per-pair global stats, one warp per pair
        if (wid < 3) {
            float mn = 1e30f, mx = -1e30f, sm = 0.f;
#pragma unroll
            for (int q = 0; q < 4; q++) {
                float4 b = __ldcg(&g_bstat[wid][lane + q * 32]);
                mn = fminf(mn, b.x); mx = fmaxf(mx, b.y); sm += b.z;
            }
#pragma unroll
            for (int o = 16; o > 0; o >>= 1) {
                mn = fminf(mn, __shfl_down_sync(0xffffffffu, mn, o));
                mx = fmaxf(mx, __shfl_down_sync(0xffffffffu, mx, o));
                sm += __shfl_down_sync(0xffffffffu, sm, o);
            }
            if (lane == 0) {
                float rg = mx - mn;
                s_mv[wid] = 0.5f * (mn + mx);
                s_sv[wid] = rg * (1.0f / 254.0f);
                s_isv[wid] = (rg > 1e-30f) ? (254.0f / rg) : 0.0f;
                s_sum[wid] = sm;
            }
        }
        __syncthreads();

        // 2) quantize the 3 x-vectors
#pragma unroll
        for (int p = 0; p < 3; p++) {
            const float* x = dir ? g_v[p] : g_u[p];
            float4 xv = __ldcg((const float4*)x + tid);
            float mv = s_mv[p], isv = s_isv[p];
            int t0 = max(-127, min(127, __float2int_rn((xv.x - mv) * isv)));
            int t1 = max(-127, min(127, __float2int_rn((xv.y - mv) * isv)));
            int t2 = max(-127, min(127, __float2int_rn((xv.z - mv) * isv)));
            int t3 = max(-127, min(127, __float2int_rn((xv.w - mv) * isv)));
            ((char4*)tsm[p])[tid] = make_char4((char)t0, (char)t1, (char)t2, (char)t3);
        }
        __syncthreads();

        // 3) per-pair row dot (dp4a int8 x int8, exact)
#pragma unroll 1
        for (int p = 0; p < 3; p++) {
            const char* M = dir ? g_S[p] : g_ST[p];
            const uint4* pr = (const uint4*)(M + (size_t)gw * NP) + lane;
            int d = 0;
#pragma unroll
            for (int t = 0; t < 8; t += 4) {
                uint4 a0 = pr[(t + 0) * 32];
                uint4 a1 = pr[(t + 1) * 32];
                uint4 a2 = pr[(t + 2) * 32];
                uint4 a3 = pr[(t + 3) * 32];
                int4 t0 = ((const int4*)tsm[p])[(t + 0) * 32 + lane];
                int4 t1 = ((const int4*)tsm[p])[(t + 1) * 32 + lane];
                int4 t2 = ((const int4*)tsm[p])[(t + 2) * 32 + lane];
                int4 t3 = ((const int4*)tsm[p])[(t + 3) * 32 + lane];
                d = __dp4a((int)a0.x, t0.x, d); d = __dp4a((int)a0.y, t0.y, d);
                d = __dp4a((int)a0.z, t0.z, d); d = __dp4a((int)a0.w, t0.w, d);
                d = __dp4a((int)a1.x, t1.x, d); d = __dp4a((int)a1.y, t1.y, d);
                d = __dp4a((int)a1.z, t1.z, d); d = __dp4a((int)a1.w, t1.w, d);
                d = __dp4a((int)a2.x, t2.x, d); d = __dp4a((int)a2.y, t2.y, d);
                d = __dp4a((int)a2.z, t2.z, d); d = __dp4a((int)a2.w, t2.w, d);
                d = __dp4a((int)a3.x, t3.x, d); d = __dp4a((int)a3.y, t3.y, d);
                d = __dp4a((int)a3.z, t3.z, d); d = __dp4a((int)a3.w, t3.w, d);
            }
            d = wsumi(d);
            if (lane == 0) {
                const int* rs = dir ? g_rsS[p] : g_rsT[p];
                float kv = (s_mv[p] * (float)rs[gw] + s_sv[p] * (float)d
                            + 64.0f * s_sum[p]) * (1.0f / 255.0f);
                float yv = MUV / (kv + EPSV);
                (dir ? g_u[p] : g_v[p])[gw] = yv;
                yvs[p][wid] = yv;
            }
        }
        __syncthreads();

        // 4) publish per-pair block stats
        if (wid < 3) {
            float v = yvs[wid][lane];
            float mn = v, mx = v, sm = v;
#pragma unroll
            for (int o = 16; o > 0; o >>= 1) {
                mn = fminf(mn, __shfl_down_sync(0xffffffffu, mn, o));
                mx = fmaxf(mx, __shfl_down_sync(0xffffffffu, mx, o));
                sm += __shfl_down_sync(0xffffffffu, sm, o);
            }
            if (lane == 0) g_bstat[wid][blockIdx.x] = make_float4(mn, mx, sm, 0.f);
        }
        bar++; gsync(bar);
    }

    // ---- loss: sum over pairs of sum_ij u_i (S_ij+64)/255 C_ij v_j ----
    float part = 0.f;
#pragma unroll 1
    for (int p = 0; p < 3; p++) {
        __syncthreads();
        ((float4*)ysm)[tid] = __ldcg((const float4*)g_v[p] + tid);
        __syncthreads();
        const uint4* ps = (const uint4*)(g_S[p] + (size_t)gw * NP) + lane;
        const int4*  pc = (const int4*)((const char*)g_C[p] + (size_t)gw * NP * 2) + lane * 2;
        float s = 0.f;
#pragma unroll
        for (int k = 0; k < 8; k++) {
            uint4 qs = ps[k * 32];
            int4 qc0 = __ldcs(&pc[k * 64]);
            int4 qc1 = __ldcs(&pc[k * 64 + 1]);
            const __half2* h0 = (const __half2*)&qc0;
            const __half2* h1 = (const __half2*)&qc1;
            int e = (lane + k * 32) * 16;
#pragma unroll
            for (int w = 0; w < 4; w++) {
                int word = ((const int*)&qs)[w];
                const __half2* hh = (w < 2) ? (h0 + 2 * w) : (h1 + 2 * (w - 2));
                float2 c0 = __half22float2(hh[0]);
                float2 c1 = __half22float2(hh[1]);
                int s0 = (word << 24) >> 24;
                int s1 = (word << 16) >> 24;
                int s2 = (word << 8)  >> 24;
                int s3 =  word        >> 24;
                int eb = e + 4 * w;
                s += (float)(s0 + 64) * c0.x * ysm[eb + 0];
                s += (float)(s1 + 64) * c0.y * ysm[eb + 1];
                s += (float)(s2 + 64) * c1.x * ysm[eb + 2];
                s += (float)(s3 + 64) * c1.y * ysm[eb + 3];
            }
        }
        s = wsumf(s);
        if (lane == 0) part += s * (1.0f / 255.0f) * __ldcg(&g_u[p][gw]);
    }
    if (lane == 0) rsm[wid] = part;
    __syncthreads();
    if (tid == 0) {
        float b = 0.f;
#pragma unroll
        for (int q = 0; q < 32; q++) b += rsm[q];
        g_part[blockIdx.x] = b;
    }
    bar++; gsync(bar);
    if (blockIdx.x == 0 && tid == 0) {
        float t = 0.f;
        for (int i = 0; i < NBLK; i++) t += __ldcg((const float*)&g_part[i]);
        g_result = t;
    }
}

// ---------------- finalize + reset barrier state ---------------------------
__global__ void fin_k(float* out) {
    if (threadIdx.x == 0) out[0] = g_result * (1.0f / 3.0f);
    if (threadIdx.x < NBLK) g_flag[threadIdx.x * 32] = 0;
}

// ---------------- launch ---------------------------------------------------
extern "C" void kernel_launch(void* const* d_in, const int* in_sizes, int n_in,
                              void* d_out, int out_size) {
    const float* z0 = (const float*)d_in[0];
    const float* z1 = (const float*)d_in[1];
    const float* z2 = (const float*)d_in[2];
    float* out = (float*)d_out;

    static int smem_set = 0;
    if (!smem_set) {
        cudaFuncSetAttribute(gemm_expK_k,
                             cudaFuncAttributeMaxDynamicSharedMemorySize, GSM_BYTES);
        smem_set = 1;
    }

    norms_k<<<1536, 256>>>(z0, z1, z2);

    const int xi[3] = { 0, 0, 1 };
    const int yi[3] = { 1, 2, 2 };
    for (int p = 0; p < 3; p++)
        gemm_expK_k<<<1024, 256, GSM_BYTES>>>(xi[p], yi[p], p);
    sink_k<<<NBLK, NTHR>>>();
    fin_k<<<1, 256>>>(out);
}

// round 13
// speedup vs baseline: 2.5736x; 1.0497x over previous
#include <cuda_runtime.h>
#include <cuda_fp16.h>
#include <cstdint>

#define NP 4096
#define DI 128
#define REGINV 20.0f          // 1/0.05
#define KQ 20.0f              // nibble quant scale: K_hat = n / 20
#define MUV (1.0f/4096.0f)
#define EPSV 1e-8f
#define NITER 100
#define NBLK 128
#define NTHR 1024
#define NWARP (NBLK*(NTHR/32))   // 4096 == NP
#define ROWB (NP/2)              // packed row bytes = 2048

#define GP 136
#define SP 144
#define CP 136
#define GSM_BYTES (2*128*SP + 128*CP*2)

// ---------------- device scratch (no allocations allowed) ----------------
__device__ char   g_S4 [3][(size_t)NP * ROWB];  // 24 MB packed nibbles
__device__ char   g_ST4[3][(size_t)NP * ROWB];  // 24 MB packed nibble transpose
__device__ __half g_C [3][(size_t)NP * NP];     // 96 MB (streamed)
__device__ __half g_zh[3][(size_t)NP * DI];     // fp16 inputs
__device__ int    g_rsS[3][NP];                 // nibble row sums
__device__ int    g_rsT[3][NP];
__device__ float  g_u[3][NP];
__device__ float  g_v[3][NP];
__device__ float  g_norm[3][NP];
__device__ float  g_part[NBLK];
__device__ float4 g_bstat[3][NBLK];
__device__ float  g_result;
__device__ int    g_flag[NBLK * 32];

__device__ __forceinline__ float wsumf(float v) {
#pragma unroll
    for (int o = 16; o > 0; o >>= 1) v += __shfl_down_sync(0xffffffffu, v, o);
    return v;
}
__device__ __forceinline__ int wsumi(int v) {
#pragma unroll
    for (int o = 16; o > 0; o >>= 1) v += __shfl_down_sync(0xffffffffu, v, o);
    return v;
}

// ---------------- one-hop grid barrier, release/acquire -------------------
__device__ __forceinline__ void gsync(int bar) {
    __syncthreads();
    if (threadIdx.x == 0) {
        __threadfence();
        asm volatile("st.release.gpu.global.b32 [%0], %1;"
                     :: "l"(&g_flag[blockIdx.x * 32]), "r"(bar) : "memory");
    }
    if (threadIdx.x < NBLK) {
        int v;
        do {
            asm volatile("ld.acquire.gpu.global.b32 %0, [%1];"
                         : "=r"(v) : "l"(&g_flag[threadIdx.x * 32]) : "memory");
        } while (v < bar);
    }
    __syncthreads();
}

// ------- row sq-norms + fp16 convert + zero rs/result ---------------------
__global__ void norms_k(const float* __restrict__ z0, const float* __restrict__ z1,
                        const float* __restrict__ z2) {
    int gt = blockIdx.x * blockDim.x + threadIdx.x;
    if (gt == 0) g_result = 0.f;
    if (gt < 3 * NP) { ((int*)g_rsS)[gt] = 0; ((int*)g_rsT)[gt] = 0; }
    int w    = gt >> 5;
    int lane = threadIdx.x & 31;
    if (w >= 3 * NP) return;
    int iz = (w < NP) ? 0 : (w < 2 * NP ? 1 : 2);
    const float* z = (iz == 0) ? z0 : (iz == 1 ? z1 : z2);
    int r = w & (NP - 1);
    float4 f = *(const float4*)(z + (size_t)r * DI + lane * 4);
    __half2 h01 = __floats2half2_rn(f.x, f.y);
    __half2 h23 = __floats2half2_rn(f.z, f.w);
    uint2 pk = { *(unsigned*)&h01, *(unsigned*)&h23 };
    *(uint2*)(g_zh[iz] + (size_t)r * DI + lane * 4) = pk;
    float s = f.x * f.x + f.y * f.y + f.z * f.z + f.w * f.w;
    s = wsumf(s);
    if (lane == 0) ((float*)g_norm)[w] = s;
}

// -------- HMMA GEMM (128x128 tile, 8 warps) -> S4, ST4, C, rowsums --------
__device__ __forceinline__ void mma16816(float* d, const unsigned* a,
                                         unsigned b0, unsigned b1) {
    asm volatile(
        "mma.sync.aligned.m16n8k16.row.col.f32.f16.f16.f32 "
        "{%0,%1,%2,%3}, {%4,%5,%6,%7}, {%8,%9}, {%0,%1,%2,%3};"
        : "+f"(d[0]), "+f"(d[1]), "+f"(d[2]), "+f"(d[3])
        : "r"(a[0]), "r"(a[1]), "r"(a[2]), "r"(a[3]), "r"(b0), "r"(b1));
}

__global__ void __launch_bounds__(256, 2) gemm_expK_k(int xi, int yi, int pr) {
    extern __shared__ __align__(16) char smraw[];
    __half* As = (__half*)smraw;
    __half* Bs = As + 128 * GP;

    const float* nx = g_norm[xi];
    const float* ny = g_norm[yi];
    const __half* Xh = g_zh[xi];
    const __half* Yh = g_zh[yi];

    const int tid = threadIdx.x;
    const int i0 = (blockIdx.x >> 5) << 7;
    const int j0 = (blockIdx.x & 31) << 7;

    {
        int r = tid >> 1, seg = (tid & 1) * 64;
#pragma unroll
        for (int q = 0; q < 8; q++) {
            *(uint4*)&As[r * GP + seg + q * 8] =
                *(const uint4*)(Xh + (size_t)(i0 + r) * DI + seg + q * 8);
            *(uint4*)&Bs[r * GP + seg + q * 8] =
                *(const uint4*)(Yh + (size_t)(j0 + r) * DI + seg + q * 8);
        }
    }
    __syncthreads();

    const int lane = tid & 31;
    const int warp = tid >> 5;
    const int gr = lane >> 2, ct = lane & 3;
    const int rb = (warp & 3) * 32;
    const int nb = (warp >> 2) * 64;

    float acc[2][8][4];
#pragma unroll
    for (int mt = 0; mt < 2; mt++)
#pragma unroll
        for (int nt = 0; nt < 8; nt++)
#pragma unroll
            for (int e = 0; e < 4; e++) acc[mt][nt][e] = 0.f;

#pragma unroll
    for (int ks = 0; ks < 8; ks++) {
        const int kb = ks * 16;
        unsigned a[2][4];
#pragma unroll
        for (int mt = 0; mt < 2; mt++) {
            int r0 = rb + mt * 16 + gr;
            a[mt][0] = *(const unsigned*)&As[r0 * GP + kb + 2 * ct];
            a[mt][1] = *(const unsigned*)&As[(r0 + 8) * GP + kb + 2 * ct];
            a[mt][2] = *(const unsigned*)&As[r0 * GP + kb + 8 + 2 * ct];
            a[mt][3] = *(const unsigned*)&As[(r0 + 8) * GP + kb + 8 + 2 * ct];
        }
#pragma unroll
        for (int nt = 0; nt < 8; nt++) {
            int n0 = nb + nt * 8 + gr;
            unsigned b0 = *(const unsigned*)&Bs[n0 * GP + kb + 2 * ct];
            unsigned b1 = *(const unsigned*)&Bs[n0 * GP + kb + 8 + 2 * ct];
            mma16816(acc[0][nt], a[0], b0, b1);
            mma16816(acc[1][nt], a[1], b0, b1);
        }
    }
    __syncthreads();

    char*   Sr = smraw;                           // [128][SP] nibble-valued bytes, row layout
    char*   Sc = smraw + 128 * SP;                // [128][SP] col layout
    __half* Cm = (__half*)(smraw + 2 * 128 * SP); // [128][CP]

#pragma unroll
    for (int mt = 0; mt < 2; mt++) {
        int ila = rb + mt * 16 + gr;
        int ilb = ila + 8;
        float nxa = __ldg(nx + i0 + ila);
        float nxb = __ldg(nx + i0 + ilb);
#pragma unroll
        for (int nt = 0; nt < 8; nt++) {
            int jl = nb + nt * 8 + 2 * ct;
            float ny0 = __ldg(ny + j0 + jl);
            float ny1 = __ldg(ny + j0 + jl + 1);
            float ca0 = fmaxf(nxa + ny0 - 2.0f * acc[mt][nt][0], 0.0f);
            float ca1 = fmaxf(nxa + ny1 - 2.0f * acc[mt][nt][1], 0.0f);
            float cb0 = fmaxf(nxb + ny0 - 2.0f * acc[mt][nt][2], 0.0f);
            float cb1 = fmaxf(nxb + ny1 - 2.0f * acc[mt][nt][3], 0.0f);
            int qa0 = min(15, __float2int_rn(__expf(-REGINV * ca0) * KQ));
            int qa1 = min(15, __float2int_rn(__expf(-REGINV * ca1) * KQ));
            int qb0 = min(15, __float2int_rn(__expf(-REGINV * cb0) * KQ));
            int qb1 = min(15, __float2int_rn(__expf(-REGINV * cb1) * KQ));
            *(short*)&Sr[ila * SP + jl] = (short)(qa0 | (qa1 << 8));
            *(short*)&Sr[ilb * SP + jl] = (short)(qb0 | (qb1 << 8));
            Sc[jl * SP + ila] = (char)qa0;       Sc[jl * SP + ilb] = (char)qb0;
            Sc[(jl + 1) * SP + ila] = (char)qa1; Sc[(jl + 1) * SP + ilb] = (char)qb1;
            __half2 ha = __floats2half2_rn(ca0, ca1);
            __half2 hb = __floats2half2_rn(cb0, cb1);
            *(unsigned*)&Cm[ila * CP + jl] = *(unsigned*)&ha;
            *(unsigned*)&Cm[ilb * CP + jl] = *(unsigned*)&hb;
        }
    }
    __syncthreads();

    // writeout: pack byte pairs-of-words -> nibbles (B0 | B1<<4), rowsum atomics, C
    {
        int r = tid >> 1, ii = (tid & 1) * 64;
        // S rows
        {
            int rs = 0;
            unsigned pk[8];
#pragma unroll
            for (int q = 0; q < 8; q++) {
                unsigned b0 = *(const unsigned*)&Sr[r * SP + ii + q * 8];
                unsigned b1 = *(const unsigned*)&Sr[r * SP + ii + q * 8 + 4];
                rs = __dp4a((int)b0, 0x01010101, rs);
                rs = __dp4a((int)b1, 0x01010101, rs);
                pk[q] = b0 | (b1 << 4);
            }
            char* dst = &g_S4[pr][(size_t)(i0 + r) * ROWB + ((j0 + ii) >> 1)];
            *(uint4*)dst        = make_uint4(pk[0], pk[1], pk[2], pk[3]);
            *(uint4*)(dst + 16) = make_uint4(pk[4], pk[5], pk[6], pk[7]);
            atomicAdd(&g_rsS[pr][i0 + r], rs);
        }
        // ST rows
        {
            int ts = 0;
            unsigned pk[8];
#pragma unroll
            for (int q = 0; q < 8; q++) {
                unsigned b0 = *(const unsigned*)&Sc[r * SP + ii + q * 8];
                unsigned b1 = *(const unsigned*)&Sc[r * SP + ii + q * 8 + 4];
                ts = __dp4a((int)b0, 0x01010101, ts);
                ts = __dp4a((int)b1, 0x01010101, ts);
                pk[q] = b0 | (b1 << 4);
            }
            char* dst = &g_ST4[pr][(size_t)(j0 + r) * ROWB + ((i0 + ii) >> 1)];
            *(uint4*)dst        = make_uint4(pk[0], pk[1], pk[2], pk[3]);
            *(uint4*)(dst + 16) = make_uint4(pk[4], pk[5], pk[6], pk[7]);
            atomicAdd(&g_rsT[pr][j0 + r], ts);
        }
#pragma unroll
        for (int q = 0; q < 8; q++)
            __stcs((uint4*)&g_C[pr][(size_t)(i0 + r) * NP + j0 + ii + q * 8],
                   *(const uint4*)&Cm[r * CP + ii + q * 8]);
    }
}
#undef ROWB
#define ROWB (NP/2)

// ---------------- persistent Sinkhorn + loss, ALL 3 pairs ------------------
#define NIBDOT(aw, tlo, thi)                                   \
    { int lo_ = (int)((aw) & 0x0F0F0F0Fu);                     \
      int hi_ = (int)(((aw) >> 4) & 0x0F0F0F0Fu);              \
      d = __dp4a(lo_, (tlo), d); d = __dp4a(hi_, (thi), d); }

__global__ void __launch_bounds__(NTHR, 1) sink_k() {
    __shared__ __align__(16) float ysm[NP];
    __shared__ __align__(16) char  tsm[3][NP];
    __shared__ float yvs[3][32];
    __shared__ float rsm[32];
    __shared__ float s_mv[3], s_sv[3], s_isv[3], s_sum[3];

    const int tid  = threadIdx.x;
    const int lane = tid & 31;
    const int wid  = tid >> 5;
    const int gw   = blockIdx.x * (NTHR / 32) + wid;   // 0..4095 == row
    int bar = 0;

    {
        int gi = blockIdx.x * NTHR + tid;
        if (gi < 3 * NP) ((float*)g_u)[gi] = 1.0f;
    }
    if (tid < 3) g_bstat[tid][blockIdx.x] = make_float4(1.0f, 1.0f, 32.0f, 0.0f);
    bar++; gsync(bar);

    for (int half = 0; half < 2 * NITER; half++) {
        const int dir = half & 1;     // 0: v = f(K^T u);  1: u = f(K v)

        if (wid < 3) {
            float mn = 1e30f, mx = -1e30f, sm = 0.f;
#pragma unroll
            for (int q = 0; q < 4; q++) {
                float4 b = __ldcg(&g_bstat[wid][lane + q * 32]);
                mn = fminf(mn, b.x); mx = fmaxf(mx, b.y); sm += b.z;
            }
#pragma unroll
            for (int o = 16; o > 0; o >>= 1) {
                mn = fminf(mn, __shfl_down_sync(0xffffffffu, mn, o));
                mx = fmaxf(mx, __shfl_down_sync(0xffffffffu, mx, o));
                sm += __shfl_down_sync(0xffffffffu, sm, o);
            }
            if (lane == 0) {
                float rg = mx - mn;
                s_mv[wid] = 0.5f * (mn + mx);
                s_sv[wid] = rg * (1.0f / 254.0f);
                s_isv[wid] = (rg > 1e-30f) ? (254.0f / rg) : 0.0f;
                s_sum[wid] = sm;
            }
        }
        __syncthreads();

#pragma unroll
        for (int p = 0; p < 3; p++) {
            const float* x = dir ? g_v[p] : g_u[p];
            float4 xv = __ldcg((const float4*)x + tid);
            float mv = s_mv[p], isv = s_isv[p];
            int t0 = max(-127, min(127, __float2int_rn((xv.x - mv) * isv)));
            int t1 = max(-127, min(127, __float2int_rn((xv.y - mv) * isv)));
            int t2 = max(-127, min(127, __float2int_rn((xv.z - mv) * isv)));
            int t3 = max(-127, min(127, __float2int_rn((xv.w - mv) * isv)));
            ((char4*)tsm[p])[tid] = make_char4((char)t0, (char)t1, (char)t2, (char)t3);
        }
        __syncthreads();

        // per-pair row dot on packed nibbles
#pragma unroll 1
        for (int p = 0; p < 3; p++) {
            const char* M = dir ? g_S4[p] : g_ST4[p];
            const uint4* pr = (const uint4*)(M + (size_t)gw * ROWB) + lane;
            const int4* tp = (const int4*)tsm[p];
            uint4 a0 = pr[0 * 32];
            uint4 a1 = pr[1 * 32];
            uint4 a2 = pr[2 * 32];
            uint4 a3 = pr[3 * 32];
            int d = 0;
#pragma unroll
            for (int k = 0; k < 4; k++) {
                uint4 a = (k == 0) ? a0 : (k == 1) ? a1 : (k == 2) ? a2 : a3;
                int4 tA = tp[(k * 32 + lane) * 2];
                int4 tB = tp[(k * 32 + lane) * 2 + 1];
                NIBDOT(a.x, tA.x, tA.y);
                NIBDOT(a.y, tA.z, tA.w);
                NIBDOT(a.z, tB.x, tB.y);
                NIBDOT(a.w, tB.z, tB.w);
            }
            d = wsumi(d);
            if (lane == 0) {
                const int* rs = dir ? g_rsS[p] : g_rsT[p];
                float kv = (s_mv[p] * (float)rs[gw] + s_sv[p] * (float)d) * (1.0f / KQ);
                float yv = MUV / (kv + EPSV);
                (dir ? g_u[p] : g_v[p])[gw] = yv;
                yvs[p][wid] = yv;
            }
        }
        __syncthreads();

        if (wid < 3) {
            float v = yvs[wid][lane];
            float mn = v, mx = v, sm = v;
#pragma unroll
            for (int o = 16; o > 0; o >>= 1) {
                mn = fminf(mn, __shfl_down_sync(0xffffffffu, mn, o));
                mx = fmaxf(mx, __shfl_down_sync(0xffffffffu, mx, o));
                sm += __shfl_down_sync(0xffffffffu, sm, o);
            }
            if (lane == 0) g_bstat[wid][blockIdx.x] = make_float4(mn, mx, sm, 0.f);
        }
        bar++; gsync(bar);
    }

    // ---- loss: sum over pairs of sum_ij u_i (n_ij/20) C_ij v_j ----
    float part = 0.f;
#pragma unroll 1
    for (int p = 0; p < 3; p++) {
        __syncthreads();
        ((float4*)ysm)[tid] = __ldcg((const float4*)g_v[p] + tid);
        __syncthreads();
        const uint4* ps = (const uint4*)(g_S4[p] + (size_t)gw * ROWB);
        const int4*  pc = (const int4*)(g_C[p] + (size_t)gw * NP);
        float s = 0.f;
#pragma unroll
        for (int k = 0; k < 4; k++) {
            uint4 qs = ps[k * 32 + lane];
            const int4* pcb = pc + (k * 32 + lane) * 4;
#pragma unroll
            for (int m = 0; m < 4; m++) {
                unsigned w = ((const unsigned*)&qs)[m];
                int4 qc = __ldcs(&pcb[m]);
                int e = ((k * 32 + lane) * 4 + m) * 8;
                unsigned lo = w & 0x0F0F0F0Fu;
                unsigned hi = (w >> 4) & 0x0F0F0F0Fu;
                const __half2* hh = (const __half2*)&qc;
                float2 c0 = __half22float2(hh[0]);
                float2 c1 = __half22float2(hh[1]);
                float2 c2 = __half22float2(hh[2]);
                float2 c3 = __half22float2(hh[3]);
                s += (float)(lo & 0xFF)         * c0.x * ysm[e + 0];
                s += (float)((lo >> 8) & 0xFF)  * c0.y * ysm[e + 1];
                s += (float)((lo >> 16) & 0xFF) * c1.x * ysm[e + 2];
                s += (float)((lo >> 24) & 0xFF) * c1.y * ysm[e + 3];
                s += (float)(hi & 0xFF)         * c2.x * ysm[e + 4];
                s += (float)((hi >> 8) & 0xFF)  * c2.y * ysm[e + 5];
                s += (float)((hi >> 16) & 0xFF) * c3.x * ysm[e + 6];
                s += (float)((hi >> 24) & 0xFF) * c3.y * ysm[e + 7];
            }
        }
        s = wsumf(s);
        if (lane == 0) part += s * (1.0f / KQ) * __ldcg(&g_u[p][gw]);
    }
    if (lane == 0) rsm[wid] = part;
    __syncthreads();
    if (tid == 0) {
        float b = 0.f;
#pragma unroll
        for (int q = 0; q < 32; q++) b += rsm[q];
        g_part[blockIdx.x] = b;
    }
    bar++; gsync(bar);
    if (blockIdx.x == 0 && tid == 0) {
        float t = 0.f;
        for (int i = 0; i < NBLK; i++) t += __ldcg((const float*)&g_part[i]);
        g_result = t;
    }
}

// ---------------- finalize + reset barrier state ---------------------------
__global__ void fin_k(float* out) {
    if (threadIdx.x == 0) out[0] = g_result * (1.0f / 3.0f);
    if (threadIdx.x < NBLK) g_flag[threadIdx.x * 32] = 0;
}

// ---------------- launch ---------------------------------------------------
extern "C" void kernel_launch(void* const* d_in, const int* in_sizes, int n_in,
                              void* d_out, int out_size) {
    const float* z0 = (const float*)d_in[0];
    const float* z1 = (const float*)d_in[1];
    const float* z2 = (const float*)d_in[2];
    float* out = (float*)d_out;

    static int smem_set = 0;
    if (!smem_set) {
        cudaFuncSetAttribute(gemm_expK_k,
                             cudaFuncAttributeMaxDynamicSharedMemorySize, GSM_BYTES);
        smem_set = 1;
    }

    norms_k<<<1536, 256>>>(z0, z1, z2);

    const int xi[3] = { 0, 0, 1 };
    const int yi[3] = { 1, 2, 2 };
    for (int p = 0; p < 3; p++)
        gemm_expK_k<<<1024, 256, GSM_BYTES>>>(xi[p], yi[p], p);
    sink_k<<<NBLK, NTHR>>>();
    fin_k<<<1, 256>>>(out);
}

// round 16
// speedup vs baseline: 2.9576x; 1.1492x over previous
#include <cuda_runtime.h>
#include <cuda_fp16.h>
#include <cstdint>

#define NP 4096
#define DI 128
#define REGINV 20.0f          // 1/0.05
#define KQ 20.0f              // nibble quant scale: K_hat = n / 20
#define MUV (1.0f/4096.0f)
#define EPSV 1e-8f
#define NITER 100
#define NBLK 128
#define NTHR 512
#define ROWB (NP/2)              // packed row bytes = 2048

#define GP 136
#define SP 144
#define CP 136
#define GSM_BYTES (2*128*SP + 128*CP*2)

// ---------------- device scratch (no allocations allowed) ----------------
__device__ char   g_S4 [3][(size_t)NP * ROWB];  // 24 MB packed nibbles
__device__ char   g_ST4[3][(size_t)NP * ROWB];  // 24 MB packed nibble transpose
__device__ __half g_C [3][(size_t)NP * NP];     // 96 MB (streamed)
__device__ __half g_zh[3][(size_t)NP * DI];     // fp16 inputs
__device__ int    g_rsS[3][NP];                 // nibble row sums
__device__ int    g_rsT[3][NP];
__device__ float  g_u[3][NP];
__device__ float  g_v[3][NP];
__device__ float  g_norm[3][NP];
__device__ float  g_part[NBLK];
__device__ float4 g_bstat[3][NBLK];
__device__ float  g_result;
__device__ int    g_flag[NBLK * 32];

__device__ __forceinline__ float wsumf(float v) {
#pragma unroll
    for (int o = 16; o > 0; o >>= 1) v += __shfl_down_sync(0xffffffffu, v, o);
    return v;
}
__device__ __forceinline__ int wsumi(int v) {
#pragma unroll
    for (int o = 16; o > 0; o >>= 1) v += __shfl_down_sync(0xffffffffu, v, o);
    return v;
}

// ---------------- one-hop grid barrier, release/acquire -------------------
__device__ __forceinline__ void gsync(int bar) {
    __syncthreads();
    if (threadIdx.x == 0) {
        __threadfence();
        asm volatile("st.release.gpu.global.b32 [%0], %1;"
                     :: "l"(&g_flag[blockIdx.x * 32]), "r"(bar) : "memory");
    }
    if (threadIdx.x < NBLK) {
        int v;
        do {
            asm volatile("ld.acquire.gpu.global.b32 %0, [%1];"
                         : "=r"(v) : "l"(&g_flag[threadIdx.x * 32]) : "memory");
        } while (v < bar);
    }
    __syncthreads();
}

// ------- row sq-norms + fp16 convert + zero rs/result ---------------------
__global__ void norms_k(const float* __restrict__ z0, const float* __restrict__ z1,
                        const float* __restrict__ z2) {
    int gt = blockIdx.x * blockDim.x + threadIdx.x;
    if (gt == 0) g_result = 0.f;
    if (gt < 3 * NP) { ((int*)g_rsS)[gt] = 0; ((int*)g_rsT)[gt] = 0; }
    int w    = gt >> 5;
    int lane = threadIdx.x & 31;
    if (w >= 3 * NP) return;
    int iz = (w < NP) ? 0 : (w < 2 * NP ? 1 : 2);
    const float* z = (iz == 0) ? z0 : (iz == 1 ? z1 : z2);
    int r = w & (NP - 1);
    float4 f = *(const float4*)(z + (size_t)r * DI + lane * 4);
    __half2 h01 = __floats2half2_rn(f.x, f.y);
    __half2 h23 = __floats2half2_rn(f.z, f.w);
    uint2 pk = { *(unsigned*)&h01, *(unsigned*)&h23 };
    *(uint2*)(g_zh[iz] + (size_t)r * DI + lane * 4) = pk;
    float s = f.x * f.x + f.y * f.y + f.z * f.z + f.w * f.w;
    s = wsumf(s);
    if (lane == 0) ((float*)g_norm)[w] = s;
}

// -------- HMMA GEMM (128x128 tile, 8 warps) -> S4, ST4, C, rowsums --------
__device__ __forceinline__ void mma16816(float* d, const unsigned* a,
                                         unsigned b0, unsigned b1) {
    asm volatile(
        "mma.sync.aligned.m16n8k16.row.col.f32.f16.f16.f32 "
        "{%0,%1,%2,%3}, {%4,%5,%6,%7}, {%8,%9}, {%0,%1,%2,%3};"
        : "+f"(d[0]), "+f"(d[1]), "+f"(d[2]), "+f"(d[3])
        : "r"(a[0]), "r"(a[1]), "r"(a[2]), "r"(a[3]), "r"(b0), "r"(b1));
}

__global__ void __launch_bounds__(256, 2) gemm_expK_k(int xi, int yi, int pr) {
    extern __shared__ __align__(16) char smraw[];
    __half* As = (__half*)smraw;
    __half* Bs = As + 128 * GP;

    const float* nx = g_norm[xi];
    const float* ny = g_norm[yi];
    const __half* Xh = g_zh[xi];
    const __half* Yh = g_zh[yi];

    const int tid = threadIdx.x;
    const int i0 = (blockIdx.x >> 5) << 7;
    const int j0 = (blockIdx.x & 31) << 7;

    {
        int r = tid >> 1, seg = (tid & 1) * 64;
#pragma unroll
        for (int q = 0; q < 8; q++) {
            *(uint4*)&As[r * GP + seg + q * 8] =
                *(const uint4*)(Xh + (size_t)(i0 + r) * DI + seg + q * 8);
            *(uint4*)&Bs[r * GP + seg + q * 8] =
                *(const uint4*)(Yh + (size_t)(j0 + r) * DI + seg + q * 8);
        }
    }
    __syncthreads();

    const int lane = tid & 31;
    const int warp = tid >> 5;
    const int gr = lane >> 2, ct = lane & 3;
    const int rb = (warp & 3) * 32;
    const int nb = (warp >> 2) * 64;

    float acc[2][8][4];
#pragma unroll
    for (int mt = 0; mt < 2; mt++)
#pragma unroll
        for (int nt = 0; nt < 8; nt++)
#pragma unroll
            for (int e = 0; e < 4; e++) acc[mt][nt][e] = 0.f;

#pragma unroll
    for (int ks = 0; ks < 8; ks++) {
        const int kb = ks * 16;
        unsigned a[2][4];
#pragma unroll
        for (int mt = 0; mt < 2; mt++) {
            int r0 = rb + mt * 16 + gr;
            a[mt][0] = *(const unsigned*)&As[r0 * GP + kb + 2 * ct];
            a[mt][1] = *(const unsigned*)&As[(r0 + 8) * GP + kb + 2 * ct];
            a[mt][2] = *(const unsigned*)&As[r0 * GP + kb + 8 + 2 * ct];
            a[mt][3] = *(const unsigned*)&As[(r0 + 8) * GP + kb + 8 + 2 * ct];
        }
#pragma unroll
        for (int nt = 0; nt < 8; nt++) {
            int n0 = nb + nt * 8 + gr;
            unsigned b0 = *(const unsigned*)&Bs[n0 * GP + kb + 2 * ct];
            unsigned b1 = *(const unsigned*)&Bs[n0 * GP + kb + 8 + 2 * ct];
            mma16816(acc[0][nt], a[0], b0, b1);
            mma16816(acc[1][nt], a[1], b0, b1);
        }
    }
    __syncthreads();

    char*   Sr = smraw;
    char*   Sc = smraw + 128 * SP;
    __half* Cm = (__half*)(smraw + 2 * 128 * SP);

#pragma unroll
    for (int mt = 0; mt < 2; mt++) {
        int ila = rb + mt * 16 + gr;
        int ilb = ila + 8;
        float nxa = __ldg(nx + i0 + ila);
        float nxb = __ldg(nx + i0 + ilb);
#pragma unroll
        for (int nt = 0; nt < 8; nt++) {
            int jl = nb + nt * 8 + 2 * ct;
            float ny0 = __ldg(ny + j0 + jl);
            float ny1 = __ldg(ny + j0 + jl + 1);
            float ca0 = fmaxf(nxa + ny0 - 2.0f * acc[mt][nt][0], 0.0f);
            float ca1 = fmaxf(nxa + ny1 - 2.0f * acc[mt][nt][1], 0.0f);
            float cb0 = fmaxf(nxb + ny0 - 2.0f * acc[mt][nt][2], 0.0f);
            float cb1 = fmaxf(nxb + ny1 - 2.0f * acc[mt][nt][3], 0.0f);
            int qa0 = min(15, __float2int_rn(__expf(-REGINV * ca0) * KQ));
            int qa1 = min(15, __float2int_rn(__expf(-REGINV * ca1) * KQ));
            int qb0 = min(15, __float2int_rn(__expf(-REGINV * cb0) * KQ));
            int qb1 = min(15, __float2int_rn(__expf(-REGINV * cb1) * KQ));
            *(short*)&Sr[ila * SP + jl] = (short)(qa0 | (qa1 << 8));
            *(short*)&Sr[ilb * SP + jl] = (short)(qb0 | (qb1 << 8));
            Sc[jl * SP + ila] = (char)qa0;       Sc[jl * SP + ilb] = (char)qb0;
            Sc[(jl + 1) * SP + ila] = (char)qa1; Sc[(jl + 1) * SP + ilb] = (char)qb1;
            __half2 ha = __floats2half2_rn(ca0, ca1);
            __half2 hb = __floats2half2_rn(cb0, cb1);
            *(unsigned*)&Cm[ila * CP + jl] = *(unsigned*)&ha;
            *(unsigned*)&Cm[ilb * CP + jl] = *(unsigned*)&hb;
        }
    }
    __syncthreads();

    {
        int r = tid >> 1, ii = (tid & 1) * 64;
        {
            int rs = 0;
            unsigned pk[8];
#pragma unroll
            for (int q = 0; q < 8; q++) {
                unsigned b0 = *(const unsigned*)&Sr[r * SP + ii + q * 8];
                unsigned b1 = *(const unsigned*)&Sr[r * SP + ii + q * 8 + 4];
                rs = __dp4a((int)b0, 0x01010101, rs);
                rs = __dp4a((int)b1, 0x01010101, rs);
                pk[q] = b0 | (b1 << 4);
            }
            char* dst = &g_S4[pr][(size_t)(i0 + r) * ROWB + ((j0 + ii) >> 1)];
            *(uint4*)dst        = make_uint4(pk[0], pk[1], pk[2], pk[3]);
            *(uint4*)(dst + 16) = make_uint4(pk[4], pk[5], pk[6], pk[7]);
            atomicAdd(&g_rsS[pr][i0 + r], rs);
        }
        {
            int ts = 0;
            unsigned pk[8];
#pragma unroll
            for (int q = 0; q < 8; q++) {
                unsigned b0 = *(const unsigned*)&Sc[r * SP + ii + q * 8];
                unsigned b1 = *(const unsigned*)&Sc[r * SP + ii + q * 8 + 4];
                ts = __dp4a((int)b0, 0x01010101, ts);
                ts = __dp4a((int)b1, 0x01010101, ts);
                pk[q] = b0 | (b1 << 4);
            }
            char* dst = &g_ST4[pr][(size_t)(j0 + r) * ROWB + ((i0 + ii) >> 1)];
            *(uint4*)dst        = make_uint4(pk[0], pk[1], pk[2], pk[3]);
            *(uint4*)(dst + 16) = make_uint4(pk[4], pk[5], pk[6], pk[7]);
            atomicAdd(&g_rsT[pr][j0 + r], ts);
        }
#pragma unroll
        for (int q = 0; q < 8; q++)
            __stcs((uint4*)&g_C[pr][(size_t)(i0 + r) * NP + j0 + ii + q * 8],
                   *(const uint4*)&Cm[r * CP + ii + q * 8]);
    }
}

// ---------------- persistent Sinkhorn + loss, ALL 3 pairs ------------------
// 2 rows per warp: x-unpack registers shared across both rows.
#define NIB2(aw, bw, tlo, thi)                                          \
    { int alo_ = (int)((aw) & 0x0F0F0F0Fu);                             \
      int ahi_ = (int)(((aw) >> 4) & 0x0F0F0F0Fu);                      \
      int blo_ = (int)((bw) & 0x0F0F0F0Fu);                             \
      int bhi_ = (int)(((bw) >> 4) & 0x0F0F0F0Fu);                      \
      d0 = __dp4a(alo_, (tlo), d0); d0 = __dp4a(ahi_, (thi), d0);       \
      d1 = __dp4a(blo_, (tlo), d1); d1 = __dp4a(bhi_, (thi), d1); }

__global__ void __launch_bounds__(NTHR, 1) sink_k() {
    __shared__ __align__(16) float ysm[NP];
    __shared__ __align__(16) char  tsm[3][NP];
    __shared__ float yvs[3][32];      // 16 warps x 2 rows
    __shared__ float rsm[16];
    __shared__ float s_mv[3], s_sv[3], s_isv[3], s_sum[3];

    const int tid  = threadIdx.x;
    const int lane = tid & 31;
    const int wid  = tid >> 5;                          // 0..15
    const int gw   = blockIdx.x * (NTHR / 32) + wid;    // 0..2047
    const int r0   = gw * 2, r1 = r0 + 1;
    int bar = 0;

    {
        int gi = blockIdx.x * NTHR + tid;
        if (gi < 3 * NP) ((float*)g_u)[gi] = 1.0f;
    }
    if (tid < 3) g_bstat[tid][blockIdx.x] = make_float4(1.0f, 1.0f, 32.0f, 0.0f);
    bar++; gsync(bar);

    for (int half = 0; half < 2 * NITER; half++) {
        const int dir = half & 1;     // 0: v = f(K^T u);  1: u = f(K v)

        // 1) per-pair global stats, one warp per pair
        if (wid < 3) {
            float mn = 1e30f, mx = -1e30f, sm = 0.f;
#pragma unroll
            for (int q = 0; q < 4; q++) {
                float4 b = __ldcg(&g_bstat[wid][lane + q * 32]);
                mn = fminf(mn, b.x); mx = fmaxf(mx, b.y); sm += b.z;
            }
#pragma unroll
            for (int o = 16; o > 0; o >>= 1) {
                mn = fminf(mn, __shfl_down_sync(0xffffffffu, mn, o));
                mx = fmaxf(mx, __shfl_down_sync(0xffffffffu, mx, o));
                sm += __shfl_down_sync(0xffffffffu, sm, o);
            }
            if (lane == 0) {
                float rg = mx - mn;
                s_mv[wid] = 0.5f * (mn + mx);
                s_sv[wid] = rg * (1.0f / 254.0f);
                s_isv[wid] = (rg > 1e-30f) ? (254.0f / rg) : 0.0f;
                s_sum[wid] = sm;
            }
        }
        __syncthreads();

        // 2) quantize the 3 x-vectors (two float4 per thread per pair)
#pragma unroll
        for (int p = 0; p < 3; p++) {
            const float* x = dir ? g_v[p] : g_u[p];
            float mv = s_mv[p], isv = s_isv[p];
#pragma unroll
            for (int q = 0; q < 2; q++) {
                int idx = tid + q * NTHR;
                float4 xv = __ldcg((const float4*)x + idx);
                int t0 = max(-127, min(127, __float2int_rn((xv.x - mv) * isv)));
                int t1 = max(-127, min(127, __float2int_rn((xv.y - mv) * isv)));
                int t2 = max(-127, min(127, __float2int_rn((xv.z - mv) * isv)));
                int t3 = max(-127, min(127, __float2int_rn((xv.w - mv) * isv)));
                ((char4*)tsm[p])[idx] = make_char4((char)t0, (char)t1, (char)t2, (char)t3);
            }
        }
        __syncthreads();

        // 3) per-pair dot for TWO rows, shared x registers
#pragma unroll 1
        for (int p = 0; p < 3; p++) {
            const char* M = dir ? g_S4[p] : g_ST4[p];
            const uint4* pr = (const uint4*)(M + (size_t)r0 * ROWB) + lane;
            // row0 chunks
            uint4 a0 = pr[0 * 32], a1 = pr[1 * 32], a2 = pr[2 * 32], a3 = pr[3 * 32];
            // row1 chunks (next 2048 bytes = +128 uint4)
            uint4 b0 = pr[128], b1 = pr[160], b2 = pr[192], b3 = pr[224];
            const int4* tp = (const int4*)tsm[p];
            int d0 = 0, d1 = 0;
#pragma unroll
            for (int k = 0; k < 4; k++) {
                uint4 a = (k == 0) ? a0 : (k == 1) ? a1 : (k == 2) ? a2 : a3;
                uint4 b = (k == 0) ? b0 : (k == 1) ? b1 : (k == 2) ? b2 : b3;
                int4 tA = tp[(k * 32 + lane) * 2];
                int4 tB = tp[(k * 32 + lane) * 2 + 1];
                NIB2(a.x, b.x, tA.x, tA.y);
                NIB2(a.y, b.y, tA.z, tA.w);
                NIB2(a.z, b.z, tB.x, tB.y);
                NIB2(a.w, b.w, tB.z, tB.w);
            }
            d0 = wsumi(d0);
            d1 = wsumi(d1);
            if (lane == 0) {
                const int* rs = dir ? g_rsS[p] : g_rsT[p];
                float* y = dir ? g_u[p] : g_v[p];
                float kv0 = (s_mv[p] * (float)rs[r0] + s_sv[p] * (float)d0) * (1.0f / KQ);
                float kv1 = (s_mv[p] * (float)rs[r1] + s_sv[p] * (float)d1) * (1.0f / KQ);
                float yv0 = MUV / (kv0 + EPSV);
                float yv1 = MUV / (kv1 + EPSV);
                y[r0] = yv0; y[r1] = yv1;
                yvs[p][wid * 2] = yv0; yvs[p][wid * 2 + 1] = yv1;
            }
        }
        __syncthreads();

        // 4) publish per-pair block stats (32 values per pair)
        if (wid < 3) {
            float v = yvs[wid][lane];
            float mn = v, mx = v, sm = v;
#pragma unroll
            for (int o = 16; o > 0; o >>= 1) {
                mn = fminf(mn, __shfl_down_sync(0xffffffffu, mn, o));
                mx = fmaxf(mx, __shfl_down_sync(0xffffffffu, mx, o));
                sm += __shfl_down_sync(0xffffffffu, sm, o);
            }
            if (lane == 0) g_bstat[wid][blockIdx.x] = make_float4(mn, mx, sm, 0.f);
        }
        bar++; gsync(bar);
    }

    // ---- loss: sum over pairs of sum_ij u_i (n_ij/20) C_ij v_j ----
    float part = 0.f;
#pragma unroll 1
    for (int p = 0; p < 3; p++) {
        __syncthreads();
#pragma unroll
        for (int q = 0; q < 2; q++)
            ((float4*)ysm)[tid + q * NTHR] = __ldcg((const float4*)g_v[p] + tid + q * NTHR);
        __syncthreads();
#pragma unroll 1
        for (int rr = 0; rr < 2; rr++) {
            int r = r0 + rr;
            const uint4* ps = (const uint4*)(g_S4[p] + (size_t)r * ROWB);
            const int4*  pc = (const int4*)(g_C[p] + (size_t)r * NP);
            float s = 0.f;
#pragma unroll
            for (int k = 0; k < 4; k++) {
                uint4 qs = ps[k * 32 + lane];
                const int4* pcb = pc + (k * 32 + lane) * 4;
#pragma unroll
                for (int m = 0; m < 4; m++) {
                    unsigned w = ((const unsigned*)&qs)[m];
                    int4 qc = __ldcs(&pcb[m]);
                    int e = ((k * 32 + lane) * 4 + m) * 8;
                    unsigned lo = w & 0x0F0F0F0Fu;
                    unsigned hi = (w >> 4) & 0x0F0F0F0Fu;
                    const __half2* hh = (const __half2*)&qc;
                    float2 c0 = __half22float2(hh[0]);
                    float2 c1 = __half22float2(hh[1]);
                    float2 c2 = __half22float2(hh[2]);
                    float2 c3 = __half22float2(hh[3]);
                    s += (float)(lo & 0xFF)         * c0.x * ysm[e + 0];
                    s += (float)((lo >> 8) & 0xFF)  * c0.y * ysm[e + 1];
                    s += (float)((lo >> 16) & 0xFF) * c1.x * ysm[e + 2];
                    s += (float)((lo >> 24) & 0xFF) * c1.y * ysm[e + 3];
                    s += (float)(hi & 0xFF)         * c2.x * ysm[e + 4];
                    s += (float)((hi >> 8) & 0xFF)  * c2.y * ysm[e + 5];
                    s += (float)((hi >> 16) & 0xFF) * c3.x * ysm[e + 6];
                    s += (float)((hi >> 24) & 0xFF) * c3.y * ysm[e + 7];
                }
            }
            s = wsumf(s);
            if (lane == 0) part += s * (1.0f / KQ) * __ldcg(&g_u[p][r]);
        }
    }
    if (lane == 0) rsm[wid] = part;
    __syncthreads();
    if (tid == 0) {
        float b = 0.f;
#pragma unroll
        for (int q = 0; q < 16; q++) b += rsm[q];
        g_part[blockIdx.x] = b;
    }
    bar++; gsync(bar);
    if (blockIdx.x == 0 && tid == 0) {
        float t = 0.f;
        for (int i = 0; i < NBLK; i++) t += __ldcg((const float*)&g_part[i]);
        g_result = t;
    }
}

// ---------------- finalize + reset barrier state ---------------------------
__global__ void fin_k(float* out) {
    if (threadIdx.x == 0) out[0] = g_result * (1.0f / 3.0f);
    if (threadIdx.x < NBLK) g_flag[threadIdx.x * 32] = 0;
}

// ---------------- launch ---------------------------------------------------
extern "C" void kernel_launch(void* const* d_in, const int* in_sizes, int n_in,
                              void* d_out, int out_size) {
    const float* z0 = (const float*)d_in[0];
    const float* z1 = (const float*)d_in[1];
    const float* z2 = (const float*)d_in[2];
    float* out = (float*)d_out;

    static int smem_set = 0;
    if (!smem_set) {
        cudaFuncSetAttribute(gemm_expK_k,
                             cudaFuncAttributeMaxDynamicSharedMemorySize, GSM_BYTES);
        smem_set = 1;
    }

    norms_k<<<1536, 256>>>(z0, z1, z2);

    const int xi[3] = { 0, 0, 1 };
    const int yi[3] = { 1, 2, 2 };
    for (int p = 0; p < 3; p++)
        gemm_expK_k<<<1024, 256, GSM_BYTES>>>(xi[p], yi[p], p);
    sink_k<<<NBLK, NTHR>>>();
    fin_k<<<1, 256>>>(out);
}